// round 7
// baseline (speedup 1.0000x reference)
#include <cuda_runtime.h>
#include <cuda_bf16.h>
#include <math.h>
#include <stdint.h>

#define TTOK 2048
#define DDIM 1024
#define TD (TTOK*DDIM)

// ---------------- scratch (static device memory; no allocations) ----------------
__device__ float g_scratch[68157440];

#define OFF_DX    ((size_t)0)
#define OFF_Z     ((size_t)TD)
#define OFF_XW    ((size_t)2*TD)
#define OFF_RKVG  ((size_t)7*TD)   // [0]=r  [1]=k  [2]=(unused)  [3]=g(silu)
#define OFF_W     ((size_t)11*TD)
#define OFF_CS    ((size_t)12*TD)
#define OFF_Y     ((size_t)17*TD)
#define OFF_XXX   ((size_t)19*TD)
#define OFF_WMID  (OFF_XXX + (size_t)TTOK*160)
// bf16 regions (sizes in float units; bf16 count = 2x)
#define OFF_ACTHI ((size_t)20*TD)                 // 4*TD bf16
#define OFF_ACTLO ((size_t)22*TD)                 // 4*TD bf16
#define OFF_WTHI  ((size_t)24*TD)                 // 5*1M bf16
#define OFF_WTLO  (OFF_WTHI + (size_t)2621440)
#define OFF_YGHI  (OFF_WTLO + (size_t)2621440)
#define OFF_YGLO  (OFF_YGHI + (size_t)(TD/2))
// attention bf16 operand arrays: 10 x TD bf16
// 0=r1h 1=r1l 2=k1h 3=k1l 4=r2h 5=r2l 6=k2h 7=k2l 8=vh 9=vl
#define OFF_BF    (OFF_YGLO + (size_t)(TD/2))

static __device__ __forceinline__ float clip60(float x) {
    return fminf(fmaxf(x, -60.f), 60.f);
}
static __device__ __forceinline__ uint32_t smem_u32(const void* p) {
    uint32_t a;
    asm("{ .reg .u64 t; cvta.to.shared.u64 t, %1; cvt.u32.u64 %0, t; }" : "=r"(a) : "l"(p));
    return a;
}

#define LDSM_X4(r, addr) \
    asm volatile("ldmatrix.sync.aligned.m8n8.x4.shared.b16 {%0,%1,%2,%3}, [%4];" \
                 : "=r"((r)[0]), "=r"((r)[1]), "=r"((r)[2]), "=r"((r)[3]) : "r"(addr))
#define LDSM_X4_T(r, addr) \
    asm volatile("ldmatrix.sync.aligned.m8n8.x4.trans.shared.b16 {%0,%1,%2,%3}, [%4];" \
                 : "=r"((r)[0]), "=r"((r)[1]), "=r"((r)[2]), "=r"((r)[3]) : "r"(addr))
#define MMA16816(d, a, b) \
    asm volatile("mma.sync.aligned.m16n8k16.row.col.f32.bf16.bf16.f32 " \
                 "{%0,%1,%2,%3}, {%4,%5,%6,%7}, {%8,%9}, {%0,%1,%2,%3};" \
                 : "+f"((d)[0]), "+f"((d)[1]), "+f"((d)[2]), "+f"((d)[3]) \
                 : "r"((a)[0]), "r"((a)[1]), "r"((a)[2]), "r"((a)[3]), \
                   "r"((b)[0]), "r"((b)[1]))
#define CPASYNC16(s, g) \
    asm volatile("cp.async.cg.shared.global [%0], [%1], 16;" :: "r"(s), "l"(g))
#define CPCOMMIT() asm volatile("cp.async.commit_group;" ::: "memory")
#define CPWAIT1()  asm volatile("cp.async.wait_group 1;" ::: "memory")
#define CPWAIT0()  asm volatile("cp.async.wait_group 0;" ::: "memory")
#define SWZ(o) ((o) ^ (((o) >> 3) & 0x70))

static __device__ __forceinline__ void split2(float a, float b,
                                              __nv_bfloat162* hi, __nv_bfloat162* lo) {
    __nv_bfloat162 h, l;
    h.x = __float2bfloat16(a);
    h.y = __float2bfloat16(b);
    l.x = __float2bfloat16(a - __bfloat162float(h.x));
    l.y = __float2bfloat16(b - __bfloat162float(h.y));
    *hi = h; *lo = l;
}

// ---------------- 1. token shift + z ----------------
__global__ __launch_bounds__(256) void prep_k(const float* __restrict__ x,
                                              const float* __restrict__ maa_x,
                                              float* __restrict__ dx,
                                              float* __restrict__ z) {
    int idx = blockIdx.x * 256 + threadIdx.x;
    if (idx >= TD) return;
    int t = idx >> 10;
    int d = idx & 1023;
    float xv = x[idx];
    float prev = (t > 0) ? x[idx - 1024] : 0.f;
    float nxt  = (t < TTOK - 1) ? x[idx + 1024] : 0.f;
    float dxv = 0.5f * (prev + nxt) - xv;
    dx[idx] = dxv;
    z[idx]  = xv + dxv * maa_x[d];
}

// ---------------- 2. xxx = tanh(z @ maa_w1) ----------------
__global__ __launch_bounds__(160) void xxx_k(const float* __restrict__ z,
                                             const float* __restrict__ w1,
                                             float* __restrict__ xxx) {
    __shared__ float zs[4][1024];
    int t0 = blockIdx.x * 4;
    int tid = threadIdx.x;
    for (int i = tid; i < 4 * 1024; i += 160) {
        int r = i >> 10, c = i & 1023;
        zs[r][c] = z[(size_t)(t0 + r) * 1024 + c];
    }
    __syncthreads();
    float acc[4] = {0.f, 0.f, 0.f, 0.f};
    for (int d = 0; d < 1024; d++) {
        float w = w1[d * 160 + tid];
        acc[0] += zs[0][d] * w;
        acc[1] += zs[1][d] * w;
        acc[2] += zs[2][d] * w;
        acc[3] += zs[3][d] * w;
    }
#pragma unroll
    for (int r = 0; r < 4; r++)
        xxx[(size_t)(t0 + r) * 160 + tid] = tanhf(acc[r]);
}

// ---------------- 3. mixer: xw fp32; xr/xk/xv/xg direct bf16 hi/lo ----------------
__global__ __launch_bounds__(256) void mix_k(const float* __restrict__ x,
                                             const float* __restrict__ dx,
                                             const float* __restrict__ xxx,
                                             const float* __restrict__ w2,
                                             const float* __restrict__ maa_w,
                                             const float* __restrict__ maa_k,
                                             const float* __restrict__ maa_v,
                                             const float* __restrict__ maa_r,
                                             const float* __restrict__ maa_g,
                                             float* __restrict__ xw,
                                             __nv_bfloat16* __restrict__ actHi,
                                             __nv_bfloat16* __restrict__ actLo) {
    __shared__ float xs[4][160];
    int t0 = blockIdx.x * 4;
    int tid = threadIdx.x;
    for (int i = tid; i < 640; i += 256) {
        int r = i / 160, c = i - r * 160;
        xs[r][c] = xxx[(size_t)(t0 + r) * 160 + c];
    }
    __syncthreads();
    int d = tid * 4;
    float4 xv[4], dxv[4];
#pragma unroll
    for (int r = 0; r < 4; r++) {
        xv[r]  = *(const float4*)(x  + (size_t)(t0 + r) * 1024 + d);
        dxv[r] = *(const float4*)(dx + (size_t)(t0 + r) * 1024 + d);
    }
#pragma unroll
    for (int f = 0; f < 5; f++) {
        float4 acc[4];
#pragma unroll
        for (int r = 0; r < 4; r++) acc[r] = make_float4(0.f, 0.f, 0.f, 0.f);
        for (int mi = 0; mi < 32; mi++) {
            float4 w = *(const float4*)(w2 + (size_t)(f * 32 + mi) * 1024 + d);
#pragma unroll
            for (int r = 0; r < 4; r++) {
                float s = xs[r][f * 32 + mi];
                acc[r].x += s * w.x; acc[r].y += s * w.y;
                acc[r].z += s * w.z; acc[r].w += s * w.w;
            }
        }
        const float* maa = (f == 0) ? maa_w : (f == 1) ? maa_k : (f == 2) ? maa_v
                         : (f == 3) ? maa_r : maa_g;
        float4 mv = *(const float4*)(maa + d);
        // slot in act arrays: r->0, k->1, v->2, g->3 (f: 3->0, 1->1, 2->2, 4->3)
        int slot = (f == 3) ? 0 : (f == 1) ? 1 : (f == 2) ? 2 : 3;
#pragma unroll
        for (int r = 0; r < 4; r++) {
            float4 o;
            o.x = xv[r].x + dxv[r].x * (mv.x + acc[r].x);
            o.y = xv[r].y + dxv[r].y * (mv.y + acc[r].y);
            o.z = xv[r].z + dxv[r].z * (mv.z + acc[r].z);
            o.w = xv[r].w + dxv[r].w * (mv.w + acc[r].w);
            if (f == 0) {
                *(float4*)(xw + (size_t)(t0 + r) * 1024 + d) = o;
            } else {
                size_t ofs = (size_t)slot * TD + (size_t)(t0 + r) * 1024 + d;
                __nv_bfloat162 h0, l0, h1, l1;
                split2(o.x, o.y, &h0, &l0);
                split2(o.z, o.w, &h1, &l1);
                *(__nv_bfloat162*)(actHi + ofs)     = h0;
                *(__nv_bfloat162*)(actHi + ofs + 2) = h1;
                *(__nv_bfloat162*)(actLo + ofs)     = l0;
                *(__nv_bfloat162*)(actLo + ofs + 2) = l1;
            }
        }
    }
}

// ---------------- weight transpose + split ----------------
__global__ __launch_bounds__(256) void conv_wt_k(const float* __restrict__ W0,
                                                 const float* __restrict__ W1,
                                                 const float* __restrict__ W2,
                                                 const float* __restrict__ W3,
                                                 const float* __restrict__ W4,
                                                 __nv_bfloat16* __restrict__ hi,
                                                 __nv_bfloat16* __restrict__ lo) {
    __shared__ float tile[32][33];
    int z = blockIdx.z;
    const float* W = (z == 0) ? W0 : (z == 1) ? W1 : (z == 2) ? W2 : (z == 3) ? W3 : W4;
    int k0 = blockIdx.x * 32, n0 = blockIdx.y * 32;
    int tx = threadIdx.x & 31, ty = threadIdx.x >> 5;
#pragma unroll
    for (int i = 0; i < 32; i += 8)
        tile[ty + i][tx] = W[(size_t)(k0 + ty + i) * 1024 + n0 + tx];
    __syncthreads();
    size_t base = (size_t)z * 1048576;
#pragma unroll
    for (int i = 0; i < 32; i += 8) {
        float v = tile[tx][ty + i];
        size_t o = base + (size_t)(n0 + ty + i) * 1024 + k0 + tx;
        __nv_bfloat16 h = __float2bfloat16(v);
        hi[o] = h;
        lo[o] = __float2bfloat16(v - __bfloat162float(h));
    }
}

// ---------------- mma.sync split-bf16 GEMM (projections / Wo) ----------------
// z==vz: write output as bf16 hi/lo (v path); else fp32 (+silu if z==siluZ)
__global__ __launch_bounds__(256, 1)
void gemm_mma_k(const __nv_bfloat16* __restrict__ aHi,
                const __nv_bfloat16* __restrict__ aLo,
                const __nv_bfloat16* __restrict__ bHi,
                const __nv_bfloat16* __restrict__ bLo,
                float* __restrict__ C, int siluZ,
                __nv_bfloat16* __restrict__ vHi,
                __nv_bfloat16* __restrict__ vLo, int vz) {
    extern __shared__ unsigned char smraw[];
    const int tid = threadIdx.x;
    const int z = blockIdx.z;
    const int bm = blockIdx.y * 128;
    const int bn = blockIdx.x * 128;
    const __nv_bfloat16* src_t[4] = {
        aHi + (size_t)z * TD, aLo + (size_t)z * TD,
        bHi + (size_t)z * 1048576, bLo + (size_t)z * 1048576 };
    float* Cz = C + (size_t)z * TD;

    const uint32_t sbase = smem_u32(smraw);
    const int w = tid >> 5, lane = tid & 31;
    const int mw = w >> 1, nw = w & 1;

    float acc[2][8][4];
#pragma unroll
    for (int mt = 0; mt < 2; mt++)
#pragma unroll
        for (int nt = 0; nt < 8; nt++)
#pragma unroll
            for (int q = 0; q < 4; q++) acc[mt][nt][q] = 0.f;

    auto issue = [&](int c) {
        int buf = c & 1;
        int k0 = c * 64;
#pragma unroll 4
        for (int i = tid; i < 4096; i += 256) {
            int tile = i >> 10;
            int idx = i & 1023;
            int row = idx >> 3, ch = idx & 7;
            int rbase = (tile < 2) ? bm : bn;
            const char* g = (const char*)src_t[tile]
                          + ((size_t)(rbase + row) * 1024 + k0) * 2 + ch * 16;
            uint32_t o = SWZ(row * 128 + ch * 16);
            CPASYNC16(sbase + buf * 65536 + tile * 16384 + o, g);
        }
        CPCOMMIT();
    };

    issue(0);
    issue(1);

    for (int c = 0; c < 16; c++) {
        if (c < 15) CPWAIT1(); else CPWAIT0();
        __syncthreads();
        uint32_t st = sbase + (c & 1) * 65536;
#pragma unroll
        for (int kk = 0; kk < 4; kk++) {
            int cb = kk * 2 + (lane >> 4);
            uint32_t ah[2][4], al[2][4];
#pragma unroll
            for (int mt = 0; mt < 2; mt++) {
                int r = mw * 32 + mt * 16 + (lane & 15);
                uint32_t o = SWZ(r * 128 + cb * 16);
                LDSM_X4(ah[mt], st + o);
                LDSM_X4(al[mt], st + 16384 + o);
            }
            uint32_t bh[8][2], bl[8][2];
#pragma unroll
            for (int p = 0; p < 4; p++) {
                int r = nw * 64 + p * 16 + (lane & 15);
                uint32_t o = SWZ(r * 128 + cb * 16);
                uint32_t t4[4];
                LDSM_X4(t4, st + 32768 + o);
                bh[2 * p][0] = t4[0]; bh[2 * p][1] = t4[2];
                bh[2 * p + 1][0] = t4[1]; bh[2 * p + 1][1] = t4[3];
                LDSM_X4(t4, st + 49152 + o);
                bl[2 * p][0] = t4[0]; bl[2 * p][1] = t4[2];
                bl[2 * p + 1][0] = t4[1]; bl[2 * p + 1][1] = t4[3];
            }
#pragma unroll
            for (int mt = 0; mt < 2; mt++)
#pragma unroll
                for (int nt = 0; nt < 8; nt++) {
                    MMA16816(acc[mt][nt], ah[mt], bh[nt]);
                    MMA16816(acc[mt][nt], ah[mt], bl[nt]);
                    MMA16816(acc[mt][nt], al[mt], bh[nt]);
                }
        }
        __syncthreads();
        if (c + 2 < 16) issue(c + 2);
    }

    bool silu = (z == siluZ);
    bool isv = (z == vz);
    int r0 = bm + mw * 32, c0 = bn + nw * 64;
#pragma unroll
    for (int mt = 0; mt < 2; mt++)
#pragma unroll
        for (int nt = 0; nt < 8; nt++) {
            float* d = acc[mt][nt];
            int row = r0 + mt * 16 + (lane >> 2);
            int col = c0 + nt * 8 + (lane & 3) * 2;
            if (isv) {
                __nv_bfloat162 h, l;
                split2(d[0], d[1], &h, &l);
                *(__nv_bfloat162*)(vHi + (size_t)row * 1024 + col) = h;
                *(__nv_bfloat162*)(vLo + (size_t)row * 1024 + col) = l;
                split2(d[2], d[3], &h, &l);
                *(__nv_bfloat162*)(vHi + (size_t)(row + 8) * 1024 + col) = h;
                *(__nv_bfloat162*)(vLo + (size_t)(row + 8) * 1024 + col) = l;
            } else {
                if (silu) {
#pragma unroll
                    for (int q = 0; q < 4; q++) d[q] = d[q] / (1.f + expf(-d[q]));
                }
                *(float2*)&Cz[(size_t)row * 1024 + col]       = make_float2(d[0], d[1]);
                *(float2*)&Cz[(size_t)(row + 8) * 1024 + col] = make_float2(d[2], d[3]);
            }
        }
}

// ---------------- 5. decay MLP stage 1 ----------------
__global__ __launch_bounds__(64) void decay1_k(const float* __restrict__ xw,
                                               const float* __restrict__ dw1,
                                               float* __restrict__ wmid) {
    __shared__ float xs[8][1024];
    int t0 = blockIdx.x * 8;
    int tid = threadIdx.x;
    for (int i = tid; i < 8 * 256; i += 64) {
        int r = i >> 8;
        int c4 = (i & 255) * 4;
        *(float4*)(&xs[r][c4]) = *(const float4*)(xw + (size_t)(t0 + r) * 1024 + c4);
    }
    __syncthreads();
    float acc[8] = {0.f, 0.f, 0.f, 0.f, 0.f, 0.f, 0.f, 0.f};
    for (int d = 0; d < 1024; d++) {
        float w = dw1[d * 64 + tid];
#pragma unroll
        for (int r = 0; r < 8; r++) acc[r] += xs[r][d] * w;
    }
#pragma unroll
    for (int r = 0; r < 8; r++)
        wmid[(size_t)(t0 + r) * 64 + tid] = tanhf(acc[r]);
}

// ---------------- 6. decay MLP stage 2 ----------------
__global__ __launch_bounds__(256) void decay2_k(const float* __restrict__ wmid,
                                                const float* __restrict__ dw2,
                                                const float* __restrict__ td,
                                                float* __restrict__ w) {
    __shared__ float ws[4][64];
    int t0 = blockIdx.x * 4;
    int tid = threadIdx.x;
    {
        int r = tid >> 6, c = tid & 63;
        ws[r][c] = wmid[(size_t)(t0 + r) * 64 + c];
    }
    __syncthreads();
    int d = tid * 4;
    float4 tdv = *(const float4*)(td + d);
    float4 acc[4];
#pragma unroll
    for (int r = 0; r < 4; r++) acc[r] = tdv;
    for (int j = 0; j < 64; j++) {
        float4 wv = *(const float4*)(dw2 + (size_t)j * 1024 + d);
#pragma unroll
        for (int r = 0; r < 4; r++) {
            float s = ws[r][j];
            acc[r].x += s * wv.x; acc[r].y += s * wv.y;
            acc[r].z += s * wv.z; acc[r].w += s * wv.w;
        }
    }
#pragma unroll
    for (int r = 0; r < 4; r++)
        *(float4*)(w + (size_t)(t0 + r) * 1024 + d) = acc[r];
}

// ---------------- 7. per-channel cumsum ----------------
__global__ __launch_bounds__(1024) void cumsum_k(const float* __restrict__ w,
                                                 float* __restrict__ cs) {
    __shared__ float seg[32][33];
    int c = threadIdx.x & 31;
    int j = threadIdx.x >> 5;
    int d = blockIdx.x * 32 + c;
    int tb = j * 64;
    float s = 0.f;
    for (int t = 0; t < 64; t++)
        s -= expf(w[(size_t)(tb + t) * 1024 + d]);
    seg[j][c] = s;
    __syncthreads();
    if (j == 0) {
        float run = 0.f;
        for (int jj = 0; jj < 32; jj++) {
            float tmp = seg[jj][c];
            seg[jj][c] = run;
            run += tmp;
        }
    }
    __syncthreads();
    float run = seg[j][c];
    for (int t = 0; t < 64; t++) {
        run -= expf(w[(size_t)(tb + t) * 1024 + d]);
        cs[(size_t)(tb + t) * 1024 + d] = run;
    }
}

// ---------------- 8. premult -> bf16 hi/lo operands ----------------
__global__ __launch_bounds__(256) void premult_bf_k(const float* __restrict__ r,
                                                    const float* __restrict__ k,
                                                    const float* __restrict__ w,
                                                    const float* __restrict__ cs,
                                                    __nv_bfloat16* __restrict__ bfB) {
    int idx = blockIdx.x * 256 + threadIdx.x;
    if (idx >= TD) return;
    int d = idx & 1023;
    size_t midoff = (size_t)(TTOK / 2) * 1024 + d;
    float csv = cs[idx];
    float csm = cs[midoff];
    float wh   = -expf(w[idx]);
    float whm  = -expf(w[midoff]);
    float csf = clip60(csv - csm);
    float csb = clip60((csv - wh) - (csm - whm));
    float rv = r[idx], kv = k[idx];
    float vals[4];
    vals[0] = rv * expf(csf);
    vals[1] = kv * expf(-csf);
    vals[2] = rv * expf(-csb);
    vals[3] = kv * expf(csb);
#pragma unroll
    for (int j = 0; j < 4; j++) {
        __nv_bfloat16 h = __float2bfloat16(vals[j]);
        bfB[(size_t)(2 * j) * TD + idx] = h;
        bfB[(size_t)(2 * j + 1) * TD + idx] = __float2bfloat16(vals[j] - __bfloat162float(h));
    }
}

// ---------------- 9. attention: M=128 i-tiles, double-buffered k/v ----------------
// smem (bytes): R1H 0, R1L 16K, R2H 32K, R2L 48K (128 rows x 128B each)
//               KV buf0 @64K, buf1 @112K: each {k1h,k1l,k2h,k2l,vh,vl} x 8K
//               AshH @160K (16K), AshL @176K (16K).  total 192K.
__global__ __launch_bounds__(256) void attn_mma_k(const __nv_bfloat16* __restrict__ bfB,
                                                  const float* __restrict__ log_tau,
                                                  float* __restrict__ y) {
    extern __shared__ unsigned char sm8[];
    __shared__ float redA[128], redS[128];
    const uint32_t sb = smem_u32(sm8);
    int h = blockIdx.y, it = blockIdx.x;
    int t0 = it * 128;
    int tid = threadIdx.x, w = tid >> 5, lane = tid & 31;
    int mw = w >> 1, nw = w & 1;   // 4 x 2 warp grid (M 32/warp, N 32/warp)
    size_t hb = (size_t)h * 64;
    float tau = expf(log_tau[h]);

    if (tid < 128) { redA[tid] = 0.f; redS[tid] = 0.f; }

    // r tiles: arrays {0,1,4,5} -> tiles 0..3 (16KB each)
    for (int i = tid; i < 4096; i += 256) {
        int tile = i >> 10, idx = i & 1023;
        int row = idx >> 3, ch = idx & 7;
        int arr = (tile & 1) + (tile >> 1) * 4;
        const char* g = (const char*)(bfB + (size_t)arr * TD
                        + (size_t)(t0 + row) * 1024 + hb) + ch * 16;
        CPASYNC16(sb + tile * 16384 + SWZ(row * 128 + ch * 16), g);
    }
    CPCOMMIT();

    auto issue_kv = [&](int jt) {
        bool nF = (jt <= 2 * it + 1), nB = (jt >= 2 * it);
        int s0 = jt * 64;
        uint32_t kb = sb + 65536 + (jt & 1) * 49152;
        for (int i = tid; i < 3072; i += 256) {
            int tile = i >> 9;
            if (tile < 2 && !nF) continue;
            if (tile >= 2 && tile < 4 && !nB) continue;
            int idx = i & 511, row = idx >> 3, ch = idx & 7;
            int arr = (tile < 4) ? (2 + (tile & 1) + (tile >> 1) * 4) : (tile + 4);
            const char* g = (const char*)(bfB + (size_t)arr * TD
                            + (size_t)(s0 + row) * 1024 + hb) + ch * 16;
            CPASYNC16(kb + tile * 8192 + SWZ(row * 128 + ch * 16), g);
        }
        CPCOMMIT();
    };
    issue_kv(0);

    float accY[2][4][4];
#pragma unroll
    for (int mt = 0; mt < 2; mt++)
#pragma unroll
        for (int nt = 0; nt < 4; nt++)
#pragma unroll
            for (int q = 0; q < 4; q++) accY[mt][nt][q] = 0.f;
    float sAl[2][2] = {{0.f, 0.f}, {0.f, 0.f}};
    float sSl[2][2] = {{0.f, 0.f}, {0.f, 0.f}};

    int grp = lane >> 2, qp = lane & 3;

    for (int jt = 0; jt < 32; jt++) {
        if (jt < 31) { issue_kv(jt + 1); CPWAIT1(); } else CPWAIT0();
        __syncthreads();
        uint32_t kb = sb + 65536 + (jt & 1) * 49152;
        bool nF = (jt <= 2 * it + 1), nB = (jt >= 2 * it);
        int s0 = jt * 64;

        // ---- pass over directions: dir=0 fwd (r1/k1, mask s<=t), dir=1 bwd ----
#pragma unroll
        for (int dir = 0; dir < 2; dir++) {
            if (dir == 0 && !nF) continue;
            if (dir == 1 && !nB) continue;
            uint32_t rbase = dir * 32768;
            uint32_t kbase = dir * 16384;
            float accS[2][4][4];
#pragma unroll
            for (int mt = 0; mt < 2; mt++)
#pragma unroll
                for (int nt = 0; nt < 4; nt++)
#pragma unroll
                    for (int q = 0; q < 4; q++) accS[mt][nt][q] = 0.f;
#pragma unroll
            for (int ks = 0; ks < 4; ks++) {
                uint32_t abyte = ks * 32 + (lane >> 4) * 16;
                uint32_t aH[2][4], aL[2][4];
#pragma unroll
                for (int mt = 0; mt < 2; mt++) {
                    uint32_t o = SWZ((mw * 32 + mt * 16 + (lane & 15)) * 128 + abyte);
                    LDSM_X4(aH[mt], sb + rbase + o);
                    LDSM_X4(aL[mt], sb + rbase + 16384 + o);
                }
                uint32_t bh[4][2], bl[4][2];
#pragma unroll
                for (int p = 0; p < 2; p++) {
                    uint32_t o = SWZ((nw * 32 + p * 16 + (lane & 15)) * 128 + abyte);
                    uint32_t t4[4], u4[4];
                    LDSM_X4(t4, kb + kbase + o);
                    LDSM_X4(u4, kb + kbase + 8192 + o);
                    bh[2 * p][0] = t4[0]; bh[2 * p][1] = t4[2];
                    bh[2 * p + 1][0] = t4[1]; bh[2 * p + 1][1] = t4[3];
                    bl[2 * p][0] = u4[0]; bl[2 * p][1] = u4[2];
                    bl[2 * p + 1][0] = u4[1]; bl[2 * p + 1][1] = u4[3];
                }
#pragma unroll
                for (int mt = 0; mt < 2; mt++)
#pragma unroll
                    for (int nt = 0; nt < 4; nt++) {
                        MMA16816(accS[mt][nt], aH[mt], bh[nt]);
                        MMA16816(accS[mt][nt], aH[mt], bl[nt]);
                        MMA16816(accS[mt][nt], aL[mt], bh[nt]);
                    }
            }
            // elementwise: mask, relu, pow, sums, stash
#pragma unroll
            for (int mt = 0; mt < 2; mt++)
#pragma unroll
                for (int nt = 0; nt < 4; nt++)
#pragma unroll
                    for (int q = 0; q < 4; q++) {
                        int trow = mw * 32 + mt * 16 + grp + (q >> 1) * 8;
                        int scol = nw * 32 + nt * 8 + qp * 2 + (q & 1);
                        int tg = t0 + trow, sg = s0 + scol;
                        bool take = (dir == 0) ? (sg <= tg) : (sg > tg);
                        if (take) {
                            float a = fmaxf(accS[mt][nt][q], 0.f);
                            sAl[mt][q >> 1] += a;
                            float ash = (a > 0.f) ? __powf(a + 1e-12f, tau) : 0.f;
                            sSl[mt][q >> 1] += ash;
                            __nv_bfloat16 hv = __float2bfloat16(ash);
                            uint32_t o = SWZ((uint32_t)(trow * 128 + scol * 2));
                            *(__nv_bfloat16*)(sm8 + 163840 + o) = hv;
                            *(__nv_bfloat16*)(sm8 + 180224 + o) =
                                __float2bfloat16(ash - __bfloat162float(hv));
                        }
                    }
        }
        __syncthreads();

        // ---- y mma: accY += Ash @ V ----
#pragma unroll
        for (int ks = 0; ks < 4; ks++) {
            uint32_t abyte = ks * 32 + (lane >> 4) * 16;
            uint32_t aH[2][4], aL[2][4];
#pragma unroll
            for (int mt = 0; mt < 2; mt++) {
                uint32_t o = SWZ((mw * 32 + mt * 16 + (lane & 15)) * 128 + abyte);
                LDSM_X4(aH[mt], sb + 163840 + o);
                LDSM_X4(aL[mt], sb + 180224 + o);
            }
            uint32_t bvh[4][2], bvl[4][2];
#pragma unroll
            for (int X = 0; X < 2; X++) {
                uint32_t ov = SWZ((ks * 16 + (lane & 15)) * 128
                                  + nw * 64 + X * 32 + (lane >> 4) * 16);
                uint32_t t4[4], u4[4];
                LDSM_X4_T(t4, kb + 32768 + ov);
                LDSM_X4_T(u4, kb + 40960 + ov);
                bvh[2 * X][0] = t4[0]; bvh[2 * X][1] = t4[1];
                bvh[2 * X + 1][0] = t4[2]; bvh[2 * X + 1][1] = t4[3];
                bvl[2 * X][0] = u4[0]; bvl[2 * X][1] = u4[1];
                bvl[2 * X + 1][0] = u4[2]; bvl[2 * X + 1][1] = u4[3];
            }
#pragma unroll
            for (int mt = 0; mt < 2; mt++)
#pragma unroll
                for (int nt = 0; nt < 4; nt++) {
                    MMA16816(accY[mt][nt], aH[mt], bvh[nt]);
                    MMA16816(accY[mt][nt], aH[mt], bvl[nt]);
                    MMA16816(accY[mt][nt], aL[mt], bvh[nt]);
                }
        }
        __syncthreads();
    }

    // ---- reduce row sums ----
#pragma unroll
    for (int mt = 0; mt < 2; mt++)
#pragma unroll
        for (int qh = 0; qh < 2; qh++) {
            float va = sAl[mt][qh], vs = sSl[mt][qh];
            va += __shfl_xor_sync(0xFFFFFFFFu, va, 1);
            va += __shfl_xor_sync(0xFFFFFFFFu, va, 2);
            vs += __shfl_xor_sync(0xFFFFFFFFu, vs, 1);
            vs += __shfl_xor_sync(0xFFFFFFFFu, vs, 2);
            if ((lane & 3) == 0) {
                int trow = mw * 32 + mt * 16 + grp + qh * 8;
                atomicAdd(&redA[trow], va);
                atomicAdd(&redS[trow], vs);
            }
        }
    __syncthreads();

    // ---- scale + write ----
#pragma unroll
    for (int mt = 0; mt < 2; mt++) {
        int r0 = mw * 32 + mt * 16 + grp;
        int r1 = r0 + 8;
        float sc0 = fmaxf(redA[r0], 1e-12f) / fmaxf(redS[r0], 1e-12f);
        float sc1 = fmaxf(redA[r1], 1e-12f) / fmaxf(redS[r1], 1e-12f);
#pragma unroll
        for (int nt = 0; nt < 4; nt++) {
            float* d = accY[mt][nt];
            int col = nw * 32 + nt * 8 + qp * 2;
            *(float2*)&y[(size_t)(t0 + r0) * 1024 + hb + col] =
                make_float2(d[0] * sc0, d[1] * sc0);
            *(float2*)&y[(size_t)(t0 + r1) * 1024 + hb + col] =
                make_float2(d[2] * sc1, d[3] * sc1);
        }
    }
}

// ---------------- 10. groupnorm + gate -> bf16 hi/lo ----------------
__global__ __launch_bounds__(256) void gnorm_k(const float* __restrict__ y,
                                               const float* __restrict__ g,
                                               const float* __restrict__ ln_g,
                                               const float* __restrict__ ln_b,
                                               __nv_bfloat16* __restrict__ ygHi,
                                               __nv_bfloat16* __restrict__ ygLo) {
    int gw = (blockIdx.x * 256 + threadIdx.x) >> 5;
    int lane = threadIdx.x & 31;
    int t = gw >> 4, h = gw & 15;
    size_t off = (size_t)t * 1024 + h * 64 + lane * 2;
    float2 vv = *(const float2*)(y + off);
    float s = vv.x + vv.y;
    float sq = vv.x * vv.x + vv.y * vv.y;
#pragma unroll
    for (int o = 16; o > 0; o >>= 1) {
        s  += __shfl_xor_sync(0xFFFFFFFFu, s, o);
        sq += __shfl_xor_sync(0xFFFFFFFFu, sq, o);
    }
    float mu = s * (1.f / 64.f);
    float var = sq * (1.f / 64.f) - mu * mu;
    float inv = rsqrtf(var + 6.4e-4f);
    int d = h * 64 + lane * 2;
    float2 gg = *(const float2*)(g + (size_t)t * 1024 + d);
    float ox = ((vv.x - mu) * inv * ln_g[d]     + ln_b[d])     * gg.x;
    float oy = ((vv.y - mu) * inv * ln_g[d + 1] + ln_b[d + 1]) * gg.y;
    __nv_bfloat162 hh, ll;
    split2(ox, oy, &hh, &ll);
    *(__nv_bfloat162*)(ygHi + off) = hh;
    *(__nv_bfloat162*)(ygLo + off) = ll;
}

// ---------------- launch ----------------
extern "C" void kernel_launch(void* const* d_in, const int* in_sizes, int n_in,
                              void* d_out, int out_size) {
    const float* x          = (const float*)d_in[0];
    const float* maa_x      = (const float*)d_in[1];
    const float* maa_w      = (const float*)d_in[2];
    const float* maa_k      = (const float*)d_in[3];
    const float* maa_v      = (const float*)d_in[4];
    const float* maa_r      = (const float*)d_in[5];
    const float* maa_g      = (const float*)d_in[6];
    const float* maa_w1     = (const float*)d_in[7];
    const float* maa_w2     = (const float*)d_in[8];
    const float* time_decay = (const float*)d_in[9];
    const float* decay_w1   = (const float*)d_in[10];
    const float* decay_w2   = (const float*)d_in[11];
    const float* log_tau    = (const float*)d_in[12];
    const float* Wr         = (const float*)d_in[13];
    const float* Wk         = (const float*)d_in[14];
    const float* Wv         = (const float*)d_in[15];
    const float* Wg         = (const float*)d_in[16];
    const float* Wo         = (const float*)d_in[17];
    const float* ln_g       = (const float*)d_in[18];
    const float* ln_b       = (const float*)d_in[19];

    float* S = nullptr;
    cudaGetSymbolAddress((void**)&S, g_scratch);
    float* dxb   = S + OFF_DX;
    float* zb    = S + OFF_Z;
    float* xwb   = S + OFF_XW;
    float* rkvg  = S + OFF_RKVG;
    float* wb    = S + OFF_W;
    float* csb   = S + OFF_CS;
    float* yb    = S + OFF_Y;
    float* xxxb  = S + OFF_XXX;
    float* wmidb = S + OFF_WMID;
    __nv_bfloat16* actHi = (__nv_bfloat16*)(S + OFF_ACTHI);
    __nv_bfloat16* actLo = (__nv_bfloat16*)(S + OFF_ACTLO);
    __nv_bfloat16* wtHi  = (__nv_bfloat16*)(S + OFF_WTHI);
    __nv_bfloat16* wtLo  = (__nv_bfloat16*)(S + OFF_WTLO);
    __nv_bfloat16* ygHi  = (__nv_bfloat16*)(S + OFF_YGHI);
    __nv_bfloat16* ygLo  = (__nv_bfloat16*)(S + OFF_YGLO);
    __nv_bfloat16* bfB   = (__nv_bfloat16*)(S + OFF_BF);

    int gemm_smem = 131072;
    cudaFuncSetAttribute(gemm_mma_k, cudaFuncAttributeMaxDynamicSharedMemorySize, gemm_smem);
    int attn_smem = 196608;
    cudaFuncSetAttribute(attn_mma_k, cudaFuncAttributeMaxDynamicSharedMemorySize, attn_smem);

    prep_k<<<(TD + 255) / 256, 256>>>(x, maa_x, dxb, zb);
    xxx_k<<<TTOK / 4, 160>>>(zb, maa_w1, xxxb);
    mix_k<<<TTOK / 4, 256>>>(x, dxb, xxxb, maa_w2,
                             maa_w, maa_k, maa_v, maa_r, maa_g, xwb, actHi, actLo);
    {
        dim3 grid(32, 32, 5);
        conv_wt_k<<<grid, 256>>>(Wr, Wk, Wv, Wg, Wo, wtHi, wtLo);
    }
    {
        dim3 grid(8, 16, 4);
        gemm_mma_k<<<grid, 256, gemm_smem>>>(actHi, actLo, wtHi, wtLo, rkvg, 3,
                                             bfB + (size_t)8 * TD, bfB + (size_t)9 * TD, 2);
    }
    decay1_k<<<TTOK / 8, 64>>>(xwb, decay_w1, wmidb);
    decay2_k<<<TTOK / 4, 256>>>(wmidb, decay_w2, time_decay, wb);
    cumsum_k<<<DDIM / 32, 1024>>>(wb, csb);
    premult_bf_k<<<(TD + 255) / 256, 256>>>(rkvg, rkvg + (size_t)TD, wb, csb, bfB);
    {
        dim3 grid(16, 16);
        attn_mma_k<<<grid, 256, attn_smem>>>(bfB, log_tau, yb);
    }
    gnorm_k<<<(TTOK * 16) / 8, 256>>>(yb, rkvg + (size_t)3 * TD, ln_g, ln_b, ygHi, ygLo);
    {
        dim3 grid(8, 16, 1);
        gemm_mma_k<<<grid, 256, gemm_smem>>>(ygHi, ygLo, wtHi + (size_t)4 * 1048576,
                                             wtLo + (size_t)4 * 1048576,
                                             (float*)d_out, -1, nullptr, nullptr, -1);
    }
}

// round 8
// speedup vs baseline: 1.1525x; 1.1525x over previous
#include <cuda_runtime.h>
#include <cuda_bf16.h>
#include <math.h>
#include <stdint.h>

#define TTOK 2048
#define DDIM 1024
#define TD (TTOK*DDIM)

// ---------------- scratch (static device memory; no allocations) ----------------
__device__ float g_scratch[68157440];

#define OFF_DX    ((size_t)0)
#define OFF_Z     ((size_t)TD)
#define OFF_XW    ((size_t)2*TD)
#define OFF_RKVG  ((size_t)7*TD)   // [0]=r  [1]=k  [2]=(unused)  [3]=g(silu)
#define OFF_W     ((size_t)11*TD)
#define OFF_CS    ((size_t)12*TD)
#define OFF_Y     ((size_t)17*TD)
#define OFF_XXX   ((size_t)19*TD)
#define OFF_WMID  (OFF_XXX + (size_t)TTOK*160)
// bf16 regions (sizes in float units; bf16 count = 2x)
#define OFF_ACTHI ((size_t)20*TD)                 // 4*TD bf16
#define OFF_ACTLO ((size_t)22*TD)                 // 4*TD bf16
#define OFF_WTHI  ((size_t)24*TD)                 // 5*1M bf16
#define OFF_WTLO  (OFF_WTHI + (size_t)2621440)
#define OFF_YGHI  (OFF_WTLO + (size_t)2621440)
#define OFF_YGLO  (OFF_YGHI + (size_t)(TD/2))
// attention bf16 operand arrays: 10 x TD bf16
// 0=r1h 1=r1l 2=k1h 3=k1l 4=r2h 5=r2l 6=k2h 7=k2l 8=vh 9=vl
#define OFF_BF    (OFF_YGLO + (size_t)(TD/2))

static __device__ __forceinline__ float clip60(float x) {
    return fminf(fmaxf(x, -60.f), 60.f);
}
static __device__ __forceinline__ uint32_t smem_u32(const void* p) {
    uint32_t a;
    asm("{ .reg .u64 t; cvta.to.shared.u64 t, %1; cvt.u32.u64 %0, t; }" : "=r"(a) : "l"(p));
    return a;
}

#define LDSM_X4(r, addr) \
    asm volatile("ldmatrix.sync.aligned.m8n8.x4.shared.b16 {%0,%1,%2,%3}, [%4];" \
                 : "=r"((r)[0]), "=r"((r)[1]), "=r"((r)[2]), "=r"((r)[3]) : "r"(addr))
#define LDSM_X4_T(r, addr) \
    asm volatile("ldmatrix.sync.aligned.m8n8.x4.trans.shared.b16 {%0,%1,%2,%3}, [%4];" \
                 : "=r"((r)[0]), "=r"((r)[1]), "=r"((r)[2]), "=r"((r)[3]) : "r"(addr))
#define MMA16816(d, a, b) \
    asm volatile("mma.sync.aligned.m16n8k16.row.col.f32.bf16.bf16.f32 " \
                 "{%0,%1,%2,%3}, {%4,%5,%6,%7}, {%8,%9}, {%0,%1,%2,%3};" \
                 : "+f"((d)[0]), "+f"((d)[1]), "+f"((d)[2]), "+f"((d)[3]) \
                 : "r"((a)[0]), "r"((a)[1]), "r"((a)[2]), "r"((a)[3]), \
                   "r"((b)[0]), "r"((b)[1]))
#define CPASYNC16(s, g) \
    asm volatile("cp.async.cg.shared.global [%0], [%1], 16;" :: "r"(s), "l"(g))
#define CPCOMMIT() asm volatile("cp.async.commit_group;" ::: "memory")
#define CPWAIT1()  asm volatile("cp.async.wait_group 1;" ::: "memory")
#define CPWAIT0()  asm volatile("cp.async.wait_group 0;" ::: "memory")
#define SWZ(o) ((o) ^ (((o) >> 3) & 0x70))

static __device__ __forceinline__ void split2(float a, float b,
                                              __nv_bfloat162* hi, __nv_bfloat162* lo) {
    __nv_bfloat162 h, l;
    h.x = __float2bfloat16(a);
    h.y = __float2bfloat16(b);
    l.x = __float2bfloat16(a - __bfloat162float(h.x));
    l.y = __float2bfloat16(b - __bfloat162float(h.y));
    *hi = h; *lo = l;
}

// ---------------- 1. token shift + z ----------------
__global__ __launch_bounds__(256) void prep_k(const float* __restrict__ x,
                                              const float* __restrict__ maa_x,
                                              float* __restrict__ dx,
                                              float* __restrict__ z) {
    int idx = blockIdx.x * 256 + threadIdx.x;
    if (idx >= TD) return;
    int t = idx >> 10;
    int d = idx & 1023;
    float xv = x[idx];
    float prev = (t > 0) ? x[idx - 1024] : 0.f;
    float nxt  = (t < TTOK - 1) ? x[idx + 1024] : 0.f;
    float dxv = 0.5f * (prev + nxt) - xv;
    dx[idx] = dxv;
    z[idx]  = xv + dxv * maa_x[d];
}

// ---------------- 2. xxx = tanh(z @ maa_w1) ----------------
__global__ __launch_bounds__(160) void xxx_k(const float* __restrict__ z,
                                             const float* __restrict__ w1,
                                             float* __restrict__ xxx) {
    __shared__ float zs[4][1024];
    int t0 = blockIdx.x * 4;
    int tid = threadIdx.x;
    for (int i = tid; i < 4 * 1024; i += 160) {
        int r = i >> 10, c = i & 1023;
        zs[r][c] = z[(size_t)(t0 + r) * 1024 + c];
    }
    __syncthreads();
    float acc[4] = {0.f, 0.f, 0.f, 0.f};
    for (int d = 0; d < 1024; d++) {
        float w = w1[d * 160 + tid];
        acc[0] += zs[0][d] * w;
        acc[1] += zs[1][d] * w;
        acc[2] += zs[2][d] * w;
        acc[3] += zs[3][d] * w;
    }
#pragma unroll
    for (int r = 0; r < 4; r++)
        xxx[(size_t)(t0 + r) * 160 + tid] = tanhf(acc[r]);
}

// ---------------- 3. mixer: xw fp32; xr/xk/xv/xg direct bf16 hi/lo ----------------
__global__ __launch_bounds__(256) void mix_k(const float* __restrict__ x,
                                             const float* __restrict__ dx,
                                             const float* __restrict__ xxx,
                                             const float* __restrict__ w2,
                                             const float* __restrict__ maa_w,
                                             const float* __restrict__ maa_k,
                                             const float* __restrict__ maa_v,
                                             const float* __restrict__ maa_r,
                                             const float* __restrict__ maa_g,
                                             float* __restrict__ xw,
                                             __nv_bfloat16* __restrict__ actHi,
                                             __nv_bfloat16* __restrict__ actLo) {
    __shared__ float xs[4][160];
    int t0 = blockIdx.x * 4;
    int tid = threadIdx.x;
    for (int i = tid; i < 640; i += 256) {
        int r = i / 160, c = i - r * 160;
        xs[r][c] = xxx[(size_t)(t0 + r) * 160 + c];
    }
    __syncthreads();
    int d = tid * 4;
    float4 xv[4], dxv[4];
#pragma unroll
    for (int r = 0; r < 4; r++) {
        xv[r]  = *(const float4*)(x  + (size_t)(t0 + r) * 1024 + d);
        dxv[r] = *(const float4*)(dx + (size_t)(t0 + r) * 1024 + d);
    }
#pragma unroll
    for (int f = 0; f < 5; f++) {
        float4 acc[4];
#pragma unroll
        for (int r = 0; r < 4; r++) acc[r] = make_float4(0.f, 0.f, 0.f, 0.f);
        for (int mi = 0; mi < 32; mi++) {
            float4 w = *(const float4*)(w2 + (size_t)(f * 32 + mi) * 1024 + d);
#pragma unroll
            for (int r = 0; r < 4; r++) {
                float s = xs[r][f * 32 + mi];
                acc[r].x += s * w.x; acc[r].y += s * w.y;
                acc[r].z += s * w.z; acc[r].w += s * w.w;
            }
        }
        const float* maa = (f == 0) ? maa_w : (f == 1) ? maa_k : (f == 2) ? maa_v
                         : (f == 3) ? maa_r : maa_g;
        float4 mv = *(const float4*)(maa + d);
        int slot = (f == 3) ? 0 : (f == 1) ? 1 : (f == 2) ? 2 : 3;
#pragma unroll
        for (int r = 0; r < 4; r++) {
            float4 o;
            o.x = xv[r].x + dxv[r].x * (mv.x + acc[r].x);
            o.y = xv[r].y + dxv[r].y * (mv.y + acc[r].y);
            o.z = xv[r].z + dxv[r].z * (mv.z + acc[r].z);
            o.w = xv[r].w + dxv[r].w * (mv.w + acc[r].w);
            if (f == 0) {
                *(float4*)(xw + (size_t)(t0 + r) * 1024 + d) = o;
            } else {
                size_t ofs = (size_t)slot * TD + (size_t)(t0 + r) * 1024 + d;
                __nv_bfloat162 h0, l0, h1, l1;
                split2(o.x, o.y, &h0, &l0);
                split2(o.z, o.w, &h1, &l1);
                *(__nv_bfloat162*)(actHi + ofs)     = h0;
                *(__nv_bfloat162*)(actHi + ofs + 2) = h1;
                *(__nv_bfloat162*)(actLo + ofs)     = l0;
                *(__nv_bfloat162*)(actLo + ofs + 2) = l1;
            }
        }
    }
}

// ---------------- weight transpose + split ----------------
__global__ __launch_bounds__(256) void conv_wt_k(const float* __restrict__ W0,
                                                 const float* __restrict__ W1,
                                                 const float* __restrict__ W2,
                                                 const float* __restrict__ W3,
                                                 const float* __restrict__ W4,
                                                 __nv_bfloat16* __restrict__ hi,
                                                 __nv_bfloat16* __restrict__ lo) {
    __shared__ float tile[32][33];
    int z = blockIdx.z;
    const float* W = (z == 0) ? W0 : (z == 1) ? W1 : (z == 2) ? W2 : (z == 3) ? W3 : W4;
    int k0 = blockIdx.x * 32, n0 = blockIdx.y * 32;
    int tx = threadIdx.x & 31, ty = threadIdx.x >> 5;
#pragma unroll
    for (int i = 0; i < 32; i += 8)
        tile[ty + i][tx] = W[(size_t)(k0 + ty + i) * 1024 + n0 + tx];
    __syncthreads();
    size_t base = (size_t)z * 1048576;
#pragma unroll
    for (int i = 0; i < 32; i += 8) {
        float v = tile[tx][ty + i];
        size_t o = base + (size_t)(n0 + ty + i) * 1024 + k0 + tx;
        __nv_bfloat16 h = __float2bfloat16(v);
        hi[o] = h;
        lo[o] = __float2bfloat16(v - __bfloat162float(h));
    }
}

// ---------------- mma.sync split-bf16 GEMM (projections / Wo) ----------------
__global__ __launch_bounds__(256, 1)
void gemm_mma_k(const __nv_bfloat16* __restrict__ aHi,
                const __nv_bfloat16* __restrict__ aLo,
                const __nv_bfloat16* __restrict__ bHi,
                const __nv_bfloat16* __restrict__ bLo,
                float* __restrict__ C, int siluZ,
                __nv_bfloat16* __restrict__ vHi,
                __nv_bfloat16* __restrict__ vLo, int vz) {
    extern __shared__ unsigned char smraw[];
    const int tid = threadIdx.x;
    const int z = blockIdx.z;
    const int bm = blockIdx.y * 128;
    const int bn = blockIdx.x * 128;
    const __nv_bfloat16* src_t[4] = {
        aHi + (size_t)z * TD, aLo + (size_t)z * TD,
        bHi + (size_t)z * 1048576, bLo + (size_t)z * 1048576 };
    float* Cz = C + (size_t)z * TD;

    const uint32_t sbase = smem_u32(smraw);
    const int w = tid >> 5, lane = tid & 31;
    const int mw = w >> 1, nw = w & 1;

    float acc[2][8][4];
#pragma unroll
    for (int mt = 0; mt < 2; mt++)
#pragma unroll
        for (int nt = 0; nt < 8; nt++)
#pragma unroll
            for (int q = 0; q < 4; q++) acc[mt][nt][q] = 0.f;

    auto issue = [&](int c) {
        int buf = c & 1;
        int k0 = c * 64;
#pragma unroll 4
        for (int i = tid; i < 4096; i += 256) {
            int tile = i >> 10;
            int idx = i & 1023;
            int row = idx >> 3, ch = idx & 7;
            int rbase = (tile < 2) ? bm : bn;
            const char* g = (const char*)src_t[tile]
                          + ((size_t)(rbase + row) * 1024 + k0) * 2 + ch * 16;
            uint32_t o = SWZ(row * 128 + ch * 16);
            CPASYNC16(sbase + buf * 65536 + tile * 16384 + o, g);
        }
        CPCOMMIT();
    };

    issue(0);
    issue(1);

    for (int c = 0; c < 16; c++) {
        if (c < 15) CPWAIT1(); else CPWAIT0();
        __syncthreads();
        uint32_t st = sbase + (c & 1) * 65536;
#pragma unroll
        for (int kk = 0; kk < 4; kk++) {
            int cb = kk * 2 + (lane >> 4);
            uint32_t ah[2][4], al[2][4];
#pragma unroll
            for (int mt = 0; mt < 2; mt++) {
                int r = mw * 32 + mt * 16 + (lane & 15);
                uint32_t o = SWZ(r * 128 + cb * 16);
                LDSM_X4(ah[mt], st + o);
                LDSM_X4(al[mt], st + 16384 + o);
            }
            uint32_t bh[8][2], bl[8][2];
#pragma unroll
            for (int p = 0; p < 4; p++) {
                int r = nw * 64 + p * 16 + (lane & 15);
                uint32_t o = SWZ(r * 128 + cb * 16);
                uint32_t t4[4];
                LDSM_X4(t4, st + 32768 + o);
                bh[2 * p][0] = t4[0]; bh[2 * p][1] = t4[2];
                bh[2 * p + 1][0] = t4[1]; bh[2 * p + 1][1] = t4[3];
                LDSM_X4(t4, st + 49152 + o);
                bl[2 * p][0] = t4[0]; bl[2 * p][1] = t4[2];
                bl[2 * p + 1][0] = t4[1]; bl[2 * p + 1][1] = t4[3];
            }
#pragma unroll
            for (int mt = 0; mt < 2; mt++)
#pragma unroll
                for (int nt = 0; nt < 8; nt++) {
                    MMA16816(acc[mt][nt], ah[mt], bh[nt]);
                    MMA16816(acc[mt][nt], ah[mt], bl[nt]);
                    MMA16816(acc[mt][nt], al[mt], bh[nt]);
                }
        }
        __syncthreads();
        if (c + 2 < 16) issue(c + 2);
    }

    bool silu = (z == siluZ);
    bool isv = (z == vz);
    int r0 = bm + mw * 32, c0 = bn + nw * 64;
#pragma unroll
    for (int mt = 0; mt < 2; mt++)
#pragma unroll
        for (int nt = 0; nt < 8; nt++) {
            float* d = acc[mt][nt];
            int row = r0 + mt * 16 + (lane >> 2);
            int col = c0 + nt * 8 + (lane & 3) * 2;
            if (isv) {
                __nv_bfloat162 h, l;
                split2(d[0], d[1], &h, &l);
                *(__nv_bfloat162*)(vHi + (size_t)row * 1024 + col) = h;
                *(__nv_bfloat162*)(vLo + (size_t)row * 1024 + col) = l;
                split2(d[2], d[3], &h, &l);
                *(__nv_bfloat162*)(vHi + (size_t)(row + 8) * 1024 + col) = h;
                *(__nv_bfloat162*)(vLo + (size_t)(row + 8) * 1024 + col) = l;
            } else {
                if (silu) {
#pragma unroll
                    for (int q = 0; q < 4; q++) d[q] = d[q] / (1.f + expf(-d[q]));
                }
                *(float2*)&Cz[(size_t)row * 1024 + col]       = make_float2(d[0], d[1]);
                *(float2*)&Cz[(size_t)(row + 8) * 1024 + col] = make_float2(d[2], d[3]);
            }
        }
}

// ---------------- 5. decay MLP stage 1 ----------------
__global__ __launch_bounds__(64) void decay1_k(const float* __restrict__ xw,
                                               const float* __restrict__ dw1,
                                               float* __restrict__ wmid) {
    __shared__ float xs[8][1024];
    int t0 = blockIdx.x * 8;
    int tid = threadIdx.x;
    for (int i = tid; i < 8 * 256; i += 64) {
        int r = i >> 8;
        int c4 = (i & 255) * 4;
        *(float4*)(&xs[r][c4]) = *(const float4*)(xw + (size_t)(t0 + r) * 1024 + c4);
    }
    __syncthreads();
    float acc[8] = {0.f, 0.f, 0.f, 0.f, 0.f, 0.f, 0.f, 0.f};
    for (int d = 0; d < 1024; d++) {
        float w = dw1[d * 64 + tid];
#pragma unroll
        for (int r = 0; r < 8; r++) acc[r] += xs[r][d] * w;
    }
#pragma unroll
    for (int r = 0; r < 8; r++)
        wmid[(size_t)(t0 + r) * 64 + tid] = tanhf(acc[r]);
}

// ---------------- 6. decay MLP stage 2 ----------------
__global__ __launch_bounds__(256) void decay2_k(const float* __restrict__ wmid,
                                                const float* __restrict__ dw2,
                                                const float* __restrict__ td,
                                                float* __restrict__ w) {
    __shared__ float ws[4][64];
    int t0 = blockIdx.x * 4;
    int tid = threadIdx.x;
    {
        int r = tid >> 6, c = tid & 63;
        ws[r][c] = wmid[(size_t)(t0 + r) * 64 + c];
    }
    __syncthreads();
    int d = tid * 4;
    float4 tdv = *(const float4*)(td + d);
    float4 acc[4];
#pragma unroll
    for (int r = 0; r < 4; r++) acc[r] = tdv;
    for (int j = 0; j < 64; j++) {
        float4 wv = *(const float4*)(dw2 + (size_t)j * 1024 + d);
#pragma unroll
        for (int r = 0; r < 4; r++) {
            float s = ws[r][j];
            acc[r].x += s * wv.x; acc[r].y += s * wv.y;
            acc[r].z += s * wv.z; acc[r].w += s * wv.w;
        }
    }
#pragma unroll
    for (int r = 0; r < 4; r++)
        *(float4*)(w + (size_t)(t0 + r) * 1024 + d) = acc[r];
}

// ---------------- 7. per-channel cumsum ----------------
__global__ __launch_bounds__(1024) void cumsum_k(const float* __restrict__ w,
                                                 float* __restrict__ cs) {
    __shared__ float seg[32][33];
    int c = threadIdx.x & 31;
    int j = threadIdx.x >> 5;
    int d = blockIdx.x * 32 + c;
    int tb = j * 64;
    float s = 0.f;
    for (int t = 0; t < 64; t++)
        s -= expf(w[(size_t)(tb + t) * 1024 + d]);
    seg[j][c] = s;
    __syncthreads();
    if (j == 0) {
        float run = 0.f;
        for (int jj = 0; jj < 32; jj++) {
            float tmp = seg[jj][c];
            seg[jj][c] = run;
            run += tmp;
        }
    }
    __syncthreads();
    float run = seg[j][c];
    for (int t = 0; t < 64; t++) {
        run -= expf(w[(size_t)(tb + t) * 1024 + d]);
        cs[(size_t)(tb + t) * 1024 + d] = run;
    }
}

// ---------------- 8. premult -> bf16 hi/lo operands ----------------
__global__ __launch_bounds__(256) void premult_bf_k(const float* __restrict__ r,
                                                    const float* __restrict__ k,
                                                    const float* __restrict__ w,
                                                    const float* __restrict__ cs,
                                                    __nv_bfloat16* __restrict__ bfB) {
    int idx = blockIdx.x * 256 + threadIdx.x;
    if (idx >= TD) return;
    int d = idx & 1023;
    size_t midoff = (size_t)(TTOK / 2) * 1024 + d;
    float csv = cs[idx];
    float csm = cs[midoff];
    float wh   = -expf(w[idx]);
    float whm  = -expf(w[midoff]);
    float csf = clip60(csv - csm);
    float csb = clip60((csv - wh) - (csm - whm));
    float rv = r[idx], kv = k[idx];
    float vals[4];
    vals[0] = rv * expf(csf);
    vals[1] = kv * expf(-csf);
    vals[2] = rv * expf(-csb);
    vals[3] = kv * expf(csb);
#pragma unroll
    for (int j = 0; j < 4; j++) {
        __nv_bfloat16 h = __float2bfloat16(vals[j]);
        bfB[(size_t)(2 * j) * TD + idx] = h;
        bfB[(size_t)(2 * j + 1) * TD + idx] = __float2bfloat16(vals[j] - __bfloat162float(h));
    }
}

// ---------------- 9. attention: mma.sync split-bf16 (round-6 shape: 64-row tiles) ----------------
// smem (bytes): R1H 0, R1L 8K, R2H 16K, R2L 24K,
//               K1H 32K, K1L 40K, K2H 48K, K2L 56K, VH 64K, VL 72K,
//               AH 80K, AL 88K.  total 96K dynamic -> 2 CTAs/SM.
__global__ __launch_bounds__(256) void attn_mma_k(const __nv_bfloat16* __restrict__ bfB,
                                                  const float* __restrict__ log_tau,
                                                  float* __restrict__ y) {
    extern __shared__ unsigned char sm8[];
    __shared__ float redA[64], redS[64];
    const uint32_t sb = smem_u32(sm8);
    int h = blockIdx.y, it = blockIdx.x;
    int t0 = it * 64;
    int tid = threadIdx.x, w = tid >> 5, lane = tid & 31;
    int mw = w >> 2, nw = w & 3;   // 2 x 4 warp grid
    size_t hb = (size_t)h * 64;
    float tau = expf(log_tau[h]);

    if (tid < 64) { redA[tid] = 0.f; redS[tid] = 0.f; }

    for (int i = tid; i < 2048; i += 256) {
        int tile = i >> 9, idx = i & 511;
        int row = idx >> 3, ch = idx & 7;
        int arr = (tile & 1) + (tile >> 1) * 4;
        const char* g = (const char*)(bfB + (size_t)arr * TD
                        + (size_t)(t0 + row) * 1024 + hb) + ch * 16;
        CPASYNC16(sb + tile * 8192 + SWZ(row * 128 + ch * 16), g);
    }
    CPCOMMIT();
    CPWAIT0();
    __syncthreads();

    float accY[2][2][4];
#pragma unroll
    for (int mt = 0; mt < 2; mt++)
#pragma unroll
        for (int nt = 0; nt < 2; nt++)
#pragma unroll
            for (int q = 0; q < 4; q++) accY[mt][nt][q] = 0.f;
    float sAl[2][2] = {{0.f, 0.f}, {0.f, 0.f}};
    float sSl[2][2] = {{0.f, 0.f}, {0.f, 0.f}};

    for (int jt = 0; jt < 32; jt++) {
        int s0 = jt * 64;
        bool needF = (jt <= it);
        bool needB = (jt >= it);
        for (int i = tid; i < 3072; i += 256) {
            int tile = i >> 9;
            if (tile < 2 && !needF) continue;
            if (tile >= 2 && tile < 4 && !needB) continue;
            int idx = i & 511, row = idx >> 3, ch = idx & 7;
            int arr = (tile < 4) ? (2 + (tile & 1) + (tile >> 1) * 4) : (tile + 4);
            const char* g = (const char*)(bfB + (size_t)arr * TD
                            + (size_t)(s0 + row) * 1024 + hb) + ch * 16;
            CPASYNC16(sb + 32768 + tile * 8192 + SWZ(row * 128 + ch * 16), g);
        }
        CPCOMMIT();
        CPWAIT0();
        __syncthreads();

        float accF[2][2][4], accB[2][2][4];
#pragma unroll
        for (int mt = 0; mt < 2; mt++)
#pragma unroll
            for (int nt = 0; nt < 2; nt++)
#pragma unroll
                for (int q = 0; q < 4; q++) { accF[mt][nt][q] = 0.f; accB[mt][nt][q] = 0.f; }

#pragma unroll
        for (int ks = 0; ks < 4; ks++) {
            uint32_t abyte = ks * 32 + (lane >> 4) * 16;
            uint32_t oB = SWZ((nw * 16 + (lane & 15)) * 128 + abyte);
            if (needF) {
                uint32_t aH[2][4], aL[2][4];
#pragma unroll
                for (int mt = 0; mt < 2; mt++) {
                    uint32_t o = SWZ((mw * 32 + mt * 16 + (lane & 15)) * 128 + abyte);
                    LDSM_X4(aH[mt], sb + o);
                    LDSM_X4(aL[mt], sb + 8192 + o);
                }
                uint32_t t4[4], u4[4];
                LDSM_X4(t4, sb + 32768 + oB);
                LDSM_X4(u4, sb + 40960 + oB);
                uint32_t bh[2][2] = {{t4[0], t4[2]}, {t4[1], t4[3]}};
                uint32_t bl[2][2] = {{u4[0], u4[2]}, {u4[1], u4[3]}};
#pragma unroll
                for (int mt = 0; mt < 2; mt++)
#pragma unroll
                    for (int nt = 0; nt < 2; nt++) {
                        MMA16816(accF[mt][nt], aH[mt], bh[nt]);
                        MMA16816(accF[mt][nt], aH[mt], bl[nt]);
                        MMA16816(accF[mt][nt], aL[mt], bh[nt]);
                    }
            }
            if (needB) {
                uint32_t aH[2][4], aL[2][4];
#pragma unroll
                for (int mt = 0; mt < 2; mt++) {
                    uint32_t o = SWZ((mw * 32 + mt * 16 + (lane & 15)) * 128 + abyte);
                    LDSM_X4(aH[mt], sb + 16384 + o);
                    LDSM_X4(aL[mt], sb + 24576 + o);
                }
                uint32_t t4[4], u4[4];
                LDSM_X4(t4, sb + 49152 + oB);
                LDSM_X4(u4, sb + 57344 + oB);
                uint32_t bh[2][2] = {{t4[0], t4[2]}, {t4[1], t4[3]}};
                uint32_t bl[2][2] = {{u4[0], u4[2]}, {u4[1], u4[3]}};
#pragma unroll
                for (int mt = 0; mt < 2; mt++)
#pragma unroll
                    for (int nt = 0; nt < 2; nt++) {
                        MMA16816(accB[mt][nt], aH[mt], bh[nt]);
                        MMA16816(accB[mt][nt], aH[mt], bl[nt]);
                        MMA16816(accB[mt][nt], aL[mt], bh[nt]);
                    }
            }
        }

        int grp = lane >> 2, qp = lane & 3;
#pragma unroll
        for (int mt = 0; mt < 2; mt++)
#pragma unroll
            for (int nt = 0; nt < 2; nt++)
#pragma unroll
                for (int q = 0; q < 4; q++) {
                    int trow = mw * 32 + mt * 16 + grp + (q >> 1) * 8;
                    int scol = nw * 16 + nt * 8 + qp * 2 + (q & 1);
                    float val;
                    if (jt < it) val = accF[mt][nt][q];
                    else if (jt > it) val = accB[mt][nt][q];
                    else val = (scol > trow) ? accB[mt][nt][q] : accF[mt][nt][q];
                    float a = fmaxf(val, 0.f);
                    sAl[mt][q >> 1] += a;
                    float ash = (a > 0.f) ? __powf(a + 1e-12f, tau) : 0.f;
                    sSl[mt][q >> 1] += ash;
                    __nv_bfloat16 hv = __float2bfloat16(ash);
                    uint32_t o = SWZ((uint32_t)(trow * 128 + scol * 2));
                    *(__nv_bfloat16*)(sm8 + 81920 + o) = hv;
                    *(__nv_bfloat16*)(sm8 + 90112 + o) =
                        __float2bfloat16(ash - __bfloat162float(hv));
                }
        __syncthreads();

#pragma unroll
        for (int ks = 0; ks < 4; ks++) {
            uint32_t abyte = ks * 32 + (lane >> 4) * 16;
            uint32_t aH[2][4], aL[2][4];
#pragma unroll
            for (int mt = 0; mt < 2; mt++) {
                uint32_t o = SWZ((mw * 32 + mt * 16 + (lane & 15)) * 128 + abyte);
                LDSM_X4(aH[mt], sb + 81920 + o);
                LDSM_X4(aL[mt], sb + 90112 + o);
            }
            uint32_t ov = SWZ((ks * 16 + (lane & 15)) * 128 + nw * 32 + (lane >> 4) * 16);
            uint32_t t4[4], u4[4];
            LDSM_X4_T(t4, sb + 65536 + ov);
            LDSM_X4_T(u4, sb + 73728 + ov);
            uint32_t bh[2][2] = {{t4[0], t4[1]}, {t4[2], t4[3]}};
            uint32_t bl[2][2] = {{u4[0], u4[1]}, {u4[2], u4[3]}};
#pragma unroll
            for (int mt = 0; mt < 2; mt++)
#pragma unroll
                for (int nt = 0; nt < 2; nt++) {
                    MMA16816(accY[mt][nt], aH[mt], bh[nt]);
                    MMA16816(accY[mt][nt], aH[mt], bl[nt]);
                    MMA16816(accY[mt][nt], aL[mt], bh[nt]);
                }
        }
        __syncthreads();
    }

    int grp = lane >> 2;
#pragma unroll
    for (int mt = 0; mt < 2; mt++)
#pragma unroll
        for (int qh = 0; qh < 2; qh++) {
            float va = sAl[mt][qh], vs = sSl[mt][qh];
            va += __shfl_xor_sync(0xFFFFFFFFu, va, 1);
            va += __shfl_xor_sync(0xFFFFFFFFu, va, 2);
            vs += __shfl_xor_sync(0xFFFFFFFFu, vs, 1);
            vs += __shfl_xor_sync(0xFFFFFFFFu, vs, 2);
            if ((lane & 3) == 0) {
                int trow = mw * 32 + mt * 16 + grp + qh * 8;
                atomicAdd(&redA[trow], va);
                atomicAdd(&redS[trow], vs);
            }
        }
    __syncthreads();

    int qp = lane & 3;
#pragma unroll
    for (int mt = 0; mt < 2; mt++) {
        int r0 = mw * 32 + mt * 16 + grp;
        int r1 = r0 + 8;
        float sc0 = fmaxf(redA[r0], 1e-12f) / fmaxf(redS[r0], 1e-12f);
        float sc1 = fmaxf(redA[r1], 1e-12f) / fmaxf(redS[r1], 1e-12f);
#pragma unroll
        for (int nt = 0; nt < 2; nt++) {
            float* d = accY[mt][nt];
            int col = nw * 16 + nt * 8 + qp * 2;
            *(float2*)&y[(size_t)(t0 + r0) * 1024 + hb + col] =
                make_float2(d[0] * sc0, d[1] * sc0);
            *(float2*)&y[(size_t)(t0 + r1) * 1024 + hb + col] =
                make_float2(d[2] * sc1, d[3] * sc1);
        }
    }
}

// ---------------- 10. groupnorm + gate -> bf16 hi/lo ----------------
__global__ __launch_bounds__(256) void gnorm_k(const float* __restrict__ y,
                                               const float* __restrict__ g,
                                               const float* __restrict__ ln_g,
                                               const float* __restrict__ ln_b,
                                               __nv_bfloat16* __restrict__ ygHi,
                                               __nv_bfloat16* __restrict__ ygLo) {
    int gw = (blockIdx.x * 256 + threadIdx.x) >> 5;
    int lane = threadIdx.x & 31;
    int t = gw >> 4, h = gw & 15;
    size_t off = (size_t)t * 1024 + h * 64 + lane * 2;
    float2 vv = *(const float2*)(y + off);
    float s = vv.x + vv.y;
    float sq = vv.x * vv.x + vv.y * vv.y;
#pragma unroll
    for (int o = 16; o > 0; o >>= 1) {
        s  += __shfl_xor_sync(0xFFFFFFFFu, s, o);
        sq += __shfl_xor_sync(0xFFFFFFFFu, sq, o);
    }
    float mu = s * (1.f / 64.f);
    float var = sq * (1.f / 64.f) - mu * mu;
    float inv = rsqrtf(var + 6.4e-4f);
    int d = h * 64 + lane * 2;
    float2 gg = *(const float2*)(g + (size_t)t * 1024 + d);
    float ox = ((vv.x - mu) * inv * ln_g[d]     + ln_b[d])     * gg.x;
    float oy = ((vv.y - mu) * inv * ln_g[d + 1] + ln_b[d + 1]) * gg.y;
    __nv_bfloat162 hh, ll;
    split2(ox, oy, &hh, &ll);
    *(__nv_bfloat162*)(ygHi + off) = hh;
    *(__nv_bfloat162*)(ygLo + off) = ll;
}

// ---------------- launch ----------------
extern "C" void kernel_launch(void* const* d_in, const int* in_sizes, int n_in,
                              void* d_out, int out_size) {
    const float* x          = (const float*)d_in[0];
    const float* maa_x      = (const float*)d_in[1];
    const float* maa_w      = (const float*)d_in[2];
    const float* maa_k      = (const float*)d_in[3];
    const float* maa_v      = (const float*)d_in[4];
    const float* maa_r      = (const float*)d_in[5];
    const float* maa_g      = (const float*)d_in[6];
    const float* maa_w1     = (const float*)d_in[7];
    const float* maa_w2     = (const float*)d_in[8];
    const float* time_decay = (const float*)d_in[9];
    const float* decay_w1   = (const float*)d_in[10];
    const float* decay_w2   = (const float*)d_in[11];
    const float* log_tau    = (const float*)d_in[12];
    const float* Wr         = (const float*)d_in[13];
    const float* Wk         = (const float*)d_in[14];
    const float* Wv         = (const float*)d_in[15];
    const float* Wg         = (const float*)d_in[16];
    const float* Wo         = (const float*)d_in[17];
    const float* ln_g       = (const float*)d_in[18];
    const float* ln_b       = (const float*)d_in[19];

    float* S = nullptr;
    cudaGetSymbolAddress((void**)&S, g_scratch);
    float* dxb   = S + OFF_DX;
    float* zb    = S + OFF_Z;
    float* xwb   = S + OFF_XW;
    float* rkvg  = S + OFF_RKVG;
    float* wb    = S + OFF_W;
    float* csb   = S + OFF_CS;
    float* yb    = S + OFF_Y;
    float* xxxb  = S + OFF_XXX;
    float* wmidb = S + OFF_WMID;
    __nv_bfloat16* actHi = (__nv_bfloat16*)(S + OFF_ACTHI);
    __nv_bfloat16* actLo = (__nv_bfloat16*)(S + OFF_ACTLO);
    __nv_bfloat16* wtHi  = (__nv_bfloat16*)(S + OFF_WTHI);
    __nv_bfloat16* wtLo  = (__nv_bfloat16*)(S + OFF_WTLO);
    __nv_bfloat16* ygHi  = (__nv_bfloat16*)(S + OFF_YGHI);
    __nv_bfloat16* ygLo  = (__nv_bfloat16*)(S + OFF_YGLO);
    __nv_bfloat16* bfB   = (__nv_bfloat16*)(S + OFF_BF);

    int gemm_smem = 131072;
    cudaFuncSetAttribute(gemm_mma_k, cudaFuncAttributeMaxDynamicSharedMemorySize, gemm_smem);
    int attn_smem = 98304;
    cudaFuncSetAttribute(attn_mma_k, cudaFuncAttributeMaxDynamicSharedMemorySize, attn_smem);

    prep_k<<<(TD + 255) / 256, 256>>>(x, maa_x, dxb, zb);
    xxx_k<<<TTOK / 4, 160>>>(zb, maa_w1, xxxb);
    mix_k<<<TTOK / 4, 256>>>(x, dxb, xxxb, maa_w2,
                             maa_w, maa_k, maa_v, maa_r, maa_g, xwb, actHi, actLo);
    {
        dim3 grid(32, 32, 5);
        conv_wt_k<<<grid, 256>>>(Wr, Wk, Wv, Wg, Wo, wtHi, wtLo);
    }
    {
        dim3 grid(8, 16, 4);
        gemm_mma_k<<<grid, 256, gemm_smem>>>(actHi, actLo, wtHi, wtLo, rkvg, 3,
                                             bfB + (size_t)8 * TD, bfB + (size_t)9 * TD, 2);
    }
    decay1_k<<<TTOK / 8, 64>>>(xwb, decay_w1, wmidb);
    decay2_k<<<TTOK / 4, 256>>>(wmidb, decay_w2, time_decay, wb);
    cumsum_k<<<DDIM / 32, 1024>>>(wb, csb);
    premult_bf_k<<<(TD + 255) / 256, 256>>>(rkvg, rkvg + (size_t)TD, wb, csb, bfB);
    {
        dim3 grid(32, 16);
        attn_mma_k<<<grid, 256, attn_smem>>>(bfB, log_tau, yb);
    }
    gnorm_k<<<(TTOK * 16) / 8, 256>>>(yb, rkvg + (size_t)3 * TD, ln_g, ln_b, ygHi, ygLo);
    {
        dim3 grid(8, 16, 1);
        gemm_mma_k<<<grid, 256, gemm_smem>>>(ygHi, ygLo, wtHi + (size_t)4 * 1048576,
                                             wtLo + (size_t)4 * 1048576,
                                             (float*)d_out, -1, nullptr, nullptr, -1);
    }
}

// round 9
// speedup vs baseline: 1.2603x; 1.0935x over previous
#include <cuda_runtime.h>
#include <cuda_bf16.h>
#include <math.h>
#include <stdint.h>

#define TTOK 2048
#define DDIM 1024
#define TD (TTOK*DDIM)

// ---------------- scratch (static device memory; no allocations) ----------------
__device__ float g_scratch[68157440];

#define OFF_DX    ((size_t)0)
#define OFF_Z     ((size_t)TD)
#define OFF_XW    ((size_t)2*TD)
#define OFF_RKVG  ((size_t)7*TD)   // [0]=r  [1]=k  [2]=(unused)  [3]=g(silu)
#define OFF_W     ((size_t)11*TD)
#define OFF_CS    ((size_t)12*TD)
#define OFF_Y     ((size_t)17*TD)
#define OFF_XXX   ((size_t)19*TD)
#define OFF_WMID  (OFF_XXX + (size_t)TTOK*160)
// bf16 regions (sizes in float units; bf16 count = 2x)
#define OFF_ACTHI ((size_t)20*TD)                 // 4*TD bf16
#define OFF_ACTLO ((size_t)22*TD)                 // 4*TD bf16
#define OFF_WTHI  ((size_t)24*TD)                 // 5*1M bf16
#define OFF_WTLO  (OFF_WTHI + (size_t)2621440)
#define OFF_YGHI  (OFF_WTLO + (size_t)2621440)
#define OFF_YGLO  (OFF_YGHI + (size_t)(TD/2))
// attention bf16 operand arrays: 10 x TD bf16
// 0=r1h 1=r1l 2=k1h 3=k1l 4=r2h 5=r2l 6=k2h 7=k2l 8=vh 9=vl
#define OFF_BF    (OFF_YGLO + (size_t)(TD/2))

static __device__ __forceinline__ float clip60(float x) {
    return fminf(fmaxf(x, -60.f), 60.f);
}
static __device__ __forceinline__ uint32_t smem_u32(const void* p) {
    uint32_t a;
    asm("{ .reg .u64 t; cvta.to.shared.u64 t, %1; cvt.u32.u64 %0, t; }" : "=r"(a) : "l"(p));
    return a;
}

#define LDSM_X4(r, addr) \
    asm volatile("ldmatrix.sync.aligned.m8n8.x4.shared.b16 {%0,%1,%2,%3}, [%4];" \
                 : "=r"((r)[0]), "=r"((r)[1]), "=r"((r)[2]), "=r"((r)[3]) : "r"(addr))
#define LDSM_X4_T(r, addr) \
    asm volatile("ldmatrix.sync.aligned.m8n8.x4.trans.shared.b16 {%0,%1,%2,%3}, [%4];" \
                 : "=r"((r)[0]), "=r"((r)[1]), "=r"((r)[2]), "=r"((r)[3]) : "r"(addr))
#define MMA16816(d, a, b) \
    asm volatile("mma.sync.aligned.m16n8k16.row.col.f32.bf16.bf16.f32 " \
                 "{%0,%1,%2,%3}, {%4,%5,%6,%7}, {%8,%9}, {%0,%1,%2,%3};" \
                 : "+f"((d)[0]), "+f"((d)[1]), "+f"((d)[2]), "+f"((d)[3]) \
                 : "r"((a)[0]), "r"((a)[1]), "r"((a)[2]), "r"((a)[3]), \
                   "r"((b)[0]), "r"((b)[1]))
#define CPASYNC16(s, g) \
    asm volatile("cp.async.cg.shared.global [%0], [%1], 16;" :: "r"(s), "l"(g))
#define CPCOMMIT() asm volatile("cp.async.commit_group;" ::: "memory")
#define CPWAIT1()  asm volatile("cp.async.wait_group 1;" ::: "memory")
#define CPWAIT0()  asm volatile("cp.async.wait_group 0;" ::: "memory")
#define SWZ(o) ((o) ^ (((o) >> 3) & 0x70))

static __device__ __forceinline__ void split2(float a, float b,
                                              __nv_bfloat162* hi, __nv_bfloat162* lo) {
    __nv_bfloat162 h, l;
    h.x = __float2bfloat16(a);
    h.y = __float2bfloat16(b);
    l.x = __float2bfloat16(a - __bfloat162float(h.x));
    l.y = __float2bfloat16(b - __bfloat162float(h.y));
    *hi = h; *lo = l;
}

// ---------------- 1. token shift + z ----------------
__global__ __launch_bounds__(256) void prep_k(const float* __restrict__ x,
                                              const float* __restrict__ maa_x,
                                              float* __restrict__ dx,
                                              float* __restrict__ z) {
    int idx = blockIdx.x * 256 + threadIdx.x;
    if (idx >= TD) return;
    int t = idx >> 10;
    int d = idx & 1023;
    float xv = x[idx];
    float prev = (t > 0) ? x[idx - 1024] : 0.f;
    float nxt  = (t < TTOK - 1) ? x[idx + 1024] : 0.f;
    float dxv = 0.5f * (prev + nxt) - xv;
    dx[idx] = dxv;
    z[idx]  = xv + dxv * maa_x[d];
}

// ---------------- 2. xxx = tanh(z @ maa_w1) ----------------
__global__ __launch_bounds__(160) void xxx_k(const float* __restrict__ z,
                                             const float* __restrict__ w1,
                                             float* __restrict__ xxx) {
    __shared__ float zs[4][1024];
    int t0 = blockIdx.x * 4;
    int tid = threadIdx.x;
    for (int i = tid; i < 4 * 1024; i += 160) {
        int r = i >> 10, c = i & 1023;
        zs[r][c] = z[(size_t)(t0 + r) * 1024 + c];
    }
    __syncthreads();
    float acc[4] = {0.f, 0.f, 0.f, 0.f};
    for (int d = 0; d < 1024; d++) {
        float w = w1[d * 160 + tid];
        acc[0] += zs[0][d] * w;
        acc[1] += zs[1][d] * w;
        acc[2] += zs[2][d] * w;
        acc[3] += zs[3][d] * w;
    }
#pragma unroll
    for (int r = 0; r < 4; r++)
        xxx[(size_t)(t0 + r) * 160 + tid] = tanhf(acc[r]);
}

// ---------------- 3. mixer: xw fp32; xr/xk/xv/xg direct bf16 hi/lo ----------------
__global__ __launch_bounds__(256) void mix_k(const float* __restrict__ x,
                                             const float* __restrict__ dx,
                                             const float* __restrict__ xxx,
                                             const float* __restrict__ w2,
                                             const float* __restrict__ maa_w,
                                             const float* __restrict__ maa_k,
                                             const float* __restrict__ maa_v,
                                             const float* __restrict__ maa_r,
                                             const float* __restrict__ maa_g,
                                             float* __restrict__ xw,
                                             __nv_bfloat16* __restrict__ actHi,
                                             __nv_bfloat16* __restrict__ actLo) {
    __shared__ float xs[4][160];
    int t0 = blockIdx.x * 4;
    int tid = threadIdx.x;
    for (int i = tid; i < 640; i += 256) {
        int r = i / 160, c = i - r * 160;
        xs[r][c] = xxx[(size_t)(t0 + r) * 160 + c];
    }
    __syncthreads();
    int d = tid * 4;
    float4 xv[4], dxv[4];
#pragma unroll
    for (int r = 0; r < 4; r++) {
        xv[r]  = *(const float4*)(x  + (size_t)(t0 + r) * 1024 + d);
        dxv[r] = *(const float4*)(dx + (size_t)(t0 + r) * 1024 + d);
    }
#pragma unroll
    for (int f = 0; f < 5; f++) {
        float4 acc[4];
#pragma unroll
        for (int r = 0; r < 4; r++) acc[r] = make_float4(0.f, 0.f, 0.f, 0.f);
        for (int mi = 0; mi < 32; mi++) {
            float4 w = *(const float4*)(w2 + (size_t)(f * 32 + mi) * 1024 + d);
#pragma unroll
            for (int r = 0; r < 4; r++) {
                float s = xs[r][f * 32 + mi];
                acc[r].x += s * w.x; acc[r].y += s * w.y;
                acc[r].z += s * w.z; acc[r].w += s * w.w;
            }
        }
        const float* maa = (f == 0) ? maa_w : (f == 1) ? maa_k : (f == 2) ? maa_v
                         : (f == 3) ? maa_r : maa_g;
        float4 mv = *(const float4*)(maa + d);
        int slot = (f == 3) ? 0 : (f == 1) ? 1 : (f == 2) ? 2 : 3;
#pragma unroll
        for (int r = 0; r < 4; r++) {
            float4 o;
            o.x = xv[r].x + dxv[r].x * (mv.x + acc[r].x);
            o.y = xv[r].y + dxv[r].y * (mv.y + acc[r].y);
            o.z = xv[r].z + dxv[r].z * (mv.z + acc[r].z);
            o.w = xv[r].w + dxv[r].w * (mv.w + acc[r].w);
            if (f == 0) {
                *(float4*)(xw + (size_t)(t0 + r) * 1024 + d) = o;
            } else {
                size_t ofs = (size_t)slot * TD + (size_t)(t0 + r) * 1024 + d;
                __nv_bfloat162 h0, l0, h1, l1;
                split2(o.x, o.y, &h0, &l0);
                split2(o.z, o.w, &h1, &l1);
                *(__nv_bfloat162*)(actHi + ofs)     = h0;
                *(__nv_bfloat162*)(actHi + ofs + 2) = h1;
                *(__nv_bfloat162*)(actLo + ofs)     = l0;
                *(__nv_bfloat162*)(actLo + ofs + 2) = l1;
            }
        }
    }
}

// ---------------- weight transpose + split ----------------
__global__ __launch_bounds__(256) void conv_wt_k(const float* __restrict__ W0,
                                                 const float* __restrict__ W1,
                                                 const float* __restrict__ W2,
                                                 const float* __restrict__ W3,
                                                 const float* __restrict__ W4,
                                                 __nv_bfloat16* __restrict__ hi,
                                                 __nv_bfloat16* __restrict__ lo) {
    __shared__ float tile[32][33];
    int z = blockIdx.z;
    const float* W = (z == 0) ? W0 : (z == 1) ? W1 : (z == 2) ? W2 : (z == 3) ? W3 : W4;
    int k0 = blockIdx.x * 32, n0 = blockIdx.y * 32;
    int tx = threadIdx.x & 31, ty = threadIdx.x >> 5;
#pragma unroll
    for (int i = 0; i < 32; i += 8)
        tile[ty + i][tx] = W[(size_t)(k0 + ty + i) * 1024 + n0 + tx];
    __syncthreads();
    size_t base = (size_t)z * 1048576;
#pragma unroll
    for (int i = 0; i < 32; i += 8) {
        float v = tile[tx][ty + i];
        size_t o = base + (size_t)(n0 + ty + i) * 1024 + k0 + tx;
        __nv_bfloat16 h = __float2bfloat16(v);
        hi[o] = h;
        lo[o] = __float2bfloat16(v - __bfloat162float(h));
    }
}

// ---------------- mma.sync split-bf16 GEMM: 128x64 CTA tile, occ 2 ----------------
// stage: AH 0, AL 16K, BH 32K, BL 40K (48KB); 2 stages = 96KB -> 2 CTAs/SM.
__global__ __launch_bounds__(256, 2)
void gemm_mma_k(const __nv_bfloat16* __restrict__ aHi,
                const __nv_bfloat16* __restrict__ aLo,
                const __nv_bfloat16* __restrict__ bHi,
                const __nv_bfloat16* __restrict__ bLo,
                float* __restrict__ C, int siluZ,
                __nv_bfloat16* __restrict__ vHi,
                __nv_bfloat16* __restrict__ vLo, int vz) {
    extern __shared__ unsigned char smraw[];
    const int tid = threadIdx.x;
    const int z = blockIdx.z;
    const int bm = blockIdx.y * 128;
    const int bn = blockIdx.x * 64;
    const __nv_bfloat16* srcA[2] = { aHi + (size_t)z * TD, aLo + (size_t)z * TD };
    const __nv_bfloat16* srcB[2] = { bHi + (size_t)z * 1048576, bLo + (size_t)z * 1048576 };
    float* Cz = C + (size_t)z * TD;

    const uint32_t sbase = smem_u32(smraw);
    const int w = tid >> 5, lane = tid & 31;
    const int mw = w >> 1, nw = w & 1;   // 4x2 warp grid: warp tile 32x32

    float acc[2][4][4];
#pragma unroll
    for (int mt = 0; mt < 2; mt++)
#pragma unroll
        for (int nt = 0; nt < 4; nt++)
#pragma unroll
            for (int q = 0; q < 4; q++) acc[mt][nt][q] = 0.f;

    auto issue = [&](int c) {
        uint32_t stg = sbase + (c & 1) * 49152;
        int k0 = c * 64;
        // A: 2 tiles x 1024 chunks; B: 2 tiles x 512 chunks
#pragma unroll 4
        for (int i = tid; i < 3072; i += 256) {
            const char* g;
            uint32_t dst;
            if (i < 2048) {
                int tile = i >> 10, idx = i & 1023;
                int row = idx >> 3, ch = idx & 7;
                g = (const char*)srcA[tile] + ((size_t)(bm + row) * 1024 + k0) * 2 + ch * 16;
                dst = stg + tile * 16384 + SWZ(row * 128 + ch * 16);
            } else {
                int j = i - 2048;
                int tile = j >> 9, idx = j & 511;
                int row = idx >> 3, ch = idx & 7;
                g = (const char*)srcB[tile] + ((size_t)(bn + row) * 1024 + k0) * 2 + ch * 16;
                dst = stg + 32768 + tile * 8192 + SWZ(row * 128 + ch * 16);
            }
            CPASYNC16(dst, g);
        }
        CPCOMMIT();
    };

    issue(0);
    issue(1);

    for (int c = 0; c < 16; c++) {
        if (c < 15) CPWAIT1(); else CPWAIT0();
        __syncthreads();
        uint32_t st = sbase + (c & 1) * 49152;
#pragma unroll
        for (int kk = 0; kk < 4; kk++) {
            int cb = kk * 2 + (lane >> 4);
            uint32_t ah[2][4], al[2][4];
#pragma unroll
            for (int mt = 0; mt < 2; mt++) {
                int r = mw * 32 + mt * 16 + (lane & 15);
                uint32_t o = SWZ(r * 128 + cb * 16);
                LDSM_X4(ah[mt], st + o);
                LDSM_X4(al[mt], st + 16384 + o);
            }
            uint32_t bh[4][2], bl[4][2];
#pragma unroll
            for (int p = 0; p < 2; p++) {
                int r = nw * 32 + p * 16 + (lane & 15);
                uint32_t o = SWZ(r * 128 + cb * 16);
                uint32_t t4[4];
                LDSM_X4(t4, st + 32768 + o);
                bh[2 * p][0] = t4[0]; bh[2 * p][1] = t4[2];
                bh[2 * p + 1][0] = t4[1]; bh[2 * p + 1][1] = t4[3];
                LDSM_X4(t4, st + 40960 + o);
                bl[2 * p][0] = t4[0]; bl[2 * p][1] = t4[2];
                bl[2 * p + 1][0] = t4[1]; bl[2 * p + 1][1] = t4[3];
            }
#pragma unroll
            for (int mt = 0; mt < 2; mt++)
#pragma unroll
                for (int nt = 0; nt < 4; nt++) {
                    MMA16816(acc[mt][nt], ah[mt], bh[nt]);
                    MMA16816(acc[mt][nt], ah[mt], bl[nt]);
                    MMA16816(acc[mt][nt], al[mt], bh[nt]);
                }
        }
        __syncthreads();
        if (c + 2 < 16) issue(c + 2);
    }

    bool silu = (z == siluZ);
    bool isv = (z == vz);
    int r0 = bm + mw * 32, c0 = bn + nw * 32;
#pragma unroll
    for (int mt = 0; mt < 2; mt++)
#pragma unroll
        for (int nt = 0; nt < 4; nt++) {
            float* d = acc[mt][nt];
            int row = r0 + mt * 16 + (lane >> 2);
            int col = c0 + nt * 8 + (lane & 3) * 2;
            if (isv) {
                __nv_bfloat162 h, l;
                split2(d[0], d[1], &h, &l);
                *(__nv_bfloat162*)(vHi + (size_t)row * 1024 + col) = h;
                *(__nv_bfloat162*)(vLo + (size_t)row * 1024 + col) = l;
                split2(d[2], d[3], &h, &l);
                *(__nv_bfloat162*)(vHi + (size_t)(row + 8) * 1024 + col) = h;
                *(__nv_bfloat162*)(vLo + (size_t)(row + 8) * 1024 + col) = l;
            } else {
                if (silu) {
#pragma unroll
                    for (int q = 0; q < 4; q++) d[q] = d[q] / (1.f + expf(-d[q]));
                }
                *(float2*)&Cz[(size_t)row * 1024 + col]       = make_float2(d[0], d[1]);
                *(float2*)&Cz[(size_t)(row + 8) * 1024 + col] = make_float2(d[2], d[3]);
            }
        }
}

// ---------------- 5. decay MLP stage 1: 256 threads, split-K partials ----------------
__global__ __launch_bounds__(256) void decay1_k(const float* __restrict__ xw,
                                                const float* __restrict__ dw1,
                                                float* __restrict__ wmid) {
    __shared__ float xs[8][1024];
    __shared__ float part[4][64][8];
    int t0 = blockIdx.x * 8;
    int tid = threadIdx.x;
    for (int i = tid; i < 8 * 256; i += 256) {
        int r = i >> 8;
        int c4 = (i & 255) * 4;
        *(float4*)(&xs[r][c4]) = *(const float4*)(xw + (size_t)(t0 + r) * 1024 + c4);
    }
    __syncthreads();
    int n = tid & 63;
    int kq = tid >> 6;
    int kbase = kq * 256;
    float acc[8] = {0.f, 0.f, 0.f, 0.f, 0.f, 0.f, 0.f, 0.f};
    for (int dd = 0; dd < 256; dd++) {
        int d = kbase + dd;
        float w = dw1[d * 64 + n];
#pragma unroll
        for (int r = 0; r < 8; r++) acc[r] += xs[r][d] * w;
    }
#pragma unroll
    for (int r = 0; r < 8; r++) part[kq][n][r] = acc[r];
    __syncthreads();
    if (tid < 512 - 256) {} // no-op keep
    for (int i = tid; i < 512; i += 256) {
        int nn = i & 63, r = i >> 6;
        float s = part[0][nn][r] + part[1][nn][r] + part[2][nn][r] + part[3][nn][r];
        wmid[(size_t)(t0 + r) * 64 + nn] = tanhf(s);
    }
}

// ---------------- 6. decay MLP stage 2 ----------------
__global__ __launch_bounds__(256) void decay2_k(const float* __restrict__ wmid,
                                                const float* __restrict__ dw2,
                                                const float* __restrict__ td,
                                                float* __restrict__ w) {
    __shared__ float ws[4][64];
    int t0 = blockIdx.x * 4;
    int tid = threadIdx.x;
    {
        int r = tid >> 6, c = tid & 63;
        ws[r][c] = wmid[(size_t)(t0 + r) * 64 + c];
    }
    __syncthreads();
    int d = tid * 4;
    float4 tdv = *(const float4*)(td + d);
    float4 acc[4];
#pragma unroll
    for (int r = 0; r < 4; r++) acc[r] = tdv;
    for (int j = 0; j < 64; j++) {
        float4 wv = *(const float4*)(dw2 + (size_t)j * 1024 + d);
#pragma unroll
        for (int r = 0; r < 4; r++) {
            float s = ws[r][j];
            acc[r].x += s * wv.x; acc[r].y += s * wv.y;
            acc[r].z += s * wv.z; acc[r].w += s * wv.w;
        }
    }
#pragma unroll
    for (int r = 0; r < 4; r++)
        *(float4*)(w + (size_t)(t0 + r) * 1024 + d) = acc[r];
}

// ---------------- 7. per-channel cumsum ----------------
__global__ __launch_bounds__(1024) void cumsum_k(const float* __restrict__ w,
                                                 float* __restrict__ cs) {
    __shared__ float seg[32][33];
    int c = threadIdx.x & 31;
    int j = threadIdx.x >> 5;
    int d = blockIdx.x * 32 + c;
    int tb = j * 64;
    float s = 0.f;
    for (int t = 0; t < 64; t++)
        s -= expf(w[(size_t)(tb + t) * 1024 + d]);
    seg[j][c] = s;
    __syncthreads();
    if (j == 0) {
        float run = 0.f;
        for (int jj = 0; jj < 32; jj++) {
            float tmp = seg[jj][c];
            seg[jj][c] = run;
            run += tmp;
        }
    }
    __syncthreads();
    float run = seg[j][c];
    for (int t = 0; t < 64; t++) {
        run -= expf(w[(size_t)(tb + t) * 1024 + d]);
        cs[(size_t)(tb + t) * 1024 + d] = run;
    }
}

// ---------------- 8. premult -> bf16 hi/lo operands ----------------
__global__ __launch_bounds__(256) void premult_bf_k(const float* __restrict__ r,
                                                    const float* __restrict__ k,
                                                    const float* __restrict__ w,
                                                    const float* __restrict__ cs,
                                                    __nv_bfloat16* __restrict__ bfB) {
    int idx = blockIdx.x * 256 + threadIdx.x;
    if (idx >= TD) return;
    int d = idx & 1023;
    size_t midoff = (size_t)(TTOK / 2) * 1024 + d;
    float csv = cs[idx];
    float csm = cs[midoff];
    float wh   = -expf(w[idx]);
    float whm  = -expf(w[midoff]);
    float csf = clip60(csv - csm);
    float csb = clip60((csv - wh) - (csm - whm));
    float rv = r[idx], kv = k[idx];
    float vals[4];
    vals[0] = rv * expf(csf);
    vals[1] = kv * expf(-csf);
    vals[2] = rv * expf(-csb);
    vals[3] = kv * expf(csb);
#pragma unroll
    for (int j = 0; j < 4; j++) {
        __nv_bfloat16 h = __float2bfloat16(vals[j]);
        bfB[(size_t)(2 * j) * TD + idx] = h;
        bfB[(size_t)(2 * j + 1) * TD + idx] = __float2bfloat16(vals[j] - __bfloat162float(h));
    }
}

// ---------------- 9. attention: mma.sync split-bf16 (64-row tiles, occ 2) ----------------
__global__ __launch_bounds__(256) void attn_mma_k(const __nv_bfloat16* __restrict__ bfB,
                                                  const float* __restrict__ log_tau,
                                                  float* __restrict__ y) {
    extern __shared__ unsigned char sm8[];
    __shared__ float redA[64], redS[64];
    const uint32_t sb = smem_u32(sm8);
    int h = blockIdx.y, it = blockIdx.x;
    int t0 = it * 64;
    int tid = threadIdx.x, w = tid >> 5, lane = tid & 31;
    int mw = w >> 2, nw = w & 3;
    size_t hb = (size_t)h * 64;
    float tau = expf(log_tau[h]);

    if (tid < 64) { redA[tid] = 0.f; redS[tid] = 0.f; }

    for (int i = tid; i < 2048; i += 256) {
        int tile = i >> 9, idx = i & 511;
        int row = idx >> 3, ch = idx & 7;
        int arr = (tile & 1) + (tile >> 1) * 4;
        const char* g = (const char*)(bfB + (size_t)arr * TD
                        + (size_t)(t0 + row) * 1024 + hb) + ch * 16;
        CPASYNC16(sb + tile * 8192 + SWZ(row * 128 + ch * 16), g);
    }
    CPCOMMIT();
    CPWAIT0();
    __syncthreads();

    float accY[2][2][4];
#pragma unroll
    for (int mt = 0; mt < 2; mt++)
#pragma unroll
        for (int nt = 0; nt < 2; nt++)
#pragma unroll
            for (int q = 0; q < 4; q++) accY[mt][nt][q] = 0.f;
    float sAl[2][2] = {{0.f, 0.f}, {0.f, 0.f}};
    float sSl[2][2] = {{0.f, 0.f}, {0.f, 0.f}};

    for (int jt = 0; jt < 32; jt++) {
        int s0 = jt * 64;
        bool needF = (jt <= it);
        bool needB = (jt >= it);
        for (int i = tid; i < 3072; i += 256) {
            int tile = i >> 9;
            if (tile < 2 && !needF) continue;
            if (tile >= 2 && tile < 4 && !needB) continue;
            int idx = i & 511, row = idx >> 3, ch = idx & 7;
            int arr = (tile < 4) ? (2 + (tile & 1) + (tile >> 1) * 4) : (tile + 4);
            const char* g = (const char*)(bfB + (size_t)arr * TD
                            + (size_t)(s0 + row) * 1024 + hb) + ch * 16;
            CPASYNC16(sb + 32768 + tile * 8192 + SWZ(row * 128 + ch * 16), g);
        }
        CPCOMMIT();
        CPWAIT0();
        __syncthreads();

        float accF[2][2][4], accB[2][2][4];
#pragma unroll
        for (int mt = 0; mt < 2; mt++)
#pragma unroll
            for (int nt = 0; nt < 2; nt++)
#pragma unroll
                for (int q = 0; q < 4; q++) { accF[mt][nt][q] = 0.f; accB[mt][nt][q] = 0.f; }

#pragma unroll
        for (int ks = 0; ks < 4; ks++) {
            uint32_t abyte = ks * 32 + (lane >> 4) * 16;
            uint32_t oB = SWZ((nw * 16 + (lane & 15)) * 128 + abyte);
            if (needF) {
                uint32_t aH[2][4], aL[2][4];
#pragma unroll
                for (int mt = 0; mt < 2; mt++) {
                    uint32_t o = SWZ((mw * 32 + mt * 16 + (lane & 15)) * 128 + abyte);
                    LDSM_X4(aH[mt], sb + o);
                    LDSM_X4(aL[mt], sb + 8192 + o);
                }
                uint32_t t4[4], u4[4];
                LDSM_X4(t4, sb + 32768 + oB);
                LDSM_X4(u4, sb + 40960 + oB);
                uint32_t bh[2][2] = {{t4[0], t4[2]}, {t4[1], t4[3]}};
                uint32_t bl[2][2] = {{u4[0], u4[2]}, {u4[1], u4[3]}};
#pragma unroll
                for (int mt = 0; mt < 2; mt++)
#pragma unroll
                    for (int nt = 0; nt < 2; nt++) {
                        MMA16816(accF[mt][nt], aH[mt], bh[nt]);
                        MMA16816(accF[mt][nt], aH[mt], bl[nt]);
                        MMA16816(accF[mt][nt], aL[mt], bh[nt]);
                    }
            }
            if (needB) {
                uint32_t aH[2][4], aL[2][4];
#pragma unroll
                for (int mt = 0; mt < 2; mt++) {
                    uint32_t o = SWZ((mw * 32 + mt * 16 + (lane & 15)) * 128 + abyte);
                    LDSM_X4(aH[mt], sb + 16384 + o);
                    LDSM_X4(aL[mt], sb + 24576 + o);
                }
                uint32_t t4[4], u4[4];
                LDSM_X4(t4, sb + 49152 + oB);
                LDSM_X4(u4, sb + 57344 + oB);
                uint32_t bh[2][2] = {{t4[0], t4[2]}, {t4[1], t4[3]}};
                uint32_t bl[2][2] = {{u4[0], u4[2]}, {u4[1], u4[3]}};
#pragma unroll
                for (int mt = 0; mt < 2; mt++)
#pragma unroll
                    for (int nt = 0; nt < 2; nt++) {
                        MMA16816(accB[mt][nt], aH[mt], bh[nt]);
                        MMA16816(accB[mt][nt], aH[mt], bl[nt]);
                        MMA16816(accB[mt][nt], aL[mt], bh[nt]);
                    }
            }
        }

        int grp = lane >> 2, qp = lane & 3;
#pragma unroll
        for (int mt = 0; mt < 2; mt++)
#pragma unroll
            for (int nt = 0; nt < 2; nt++)
#pragma unroll
                for (int q = 0; q < 4; q++) {
                    int trow = mw * 32 + mt * 16 + grp + (q >> 1) * 8;
                    int scol = nw * 16 + nt * 8 + qp * 2 + (q & 1);
                    float val;
                    if (jt < it) val = accF[mt][nt][q];
                    else if (jt > it) val = accB[mt][nt][q];
                    else val = (scol > trow) ? accB[mt][nt][q] : accF[mt][nt][q];
                    float a = fmaxf(val, 0.f);
                    sAl[mt][q >> 1] += a;
                    float ash = (a > 0.f) ? __powf(a + 1e-12f, tau) : 0.f;
                    sSl[mt][q >> 1] += ash;
                    __nv_bfloat16 hv = __float2bfloat16(ash);
                    uint32_t o = SWZ((uint32_t)(trow * 128 + scol * 2));
                    *(__nv_bfloat16*)(sm8 + 81920 + o) = hv;
                    *(__nv_bfloat16*)(sm8 + 90112 + o) =
                        __float2bfloat16(ash - __bfloat162float(hv));
                }
        __syncthreads();

#pragma unroll
        for (int ks = 0; ks < 4; ks++) {
            uint32_t abyte = ks * 32 + (lane >> 4) * 16;
            uint32_t aH[2][4], aL[2][4];
#pragma unroll
            for (int mt = 0; mt < 2; mt++) {
                uint32_t o = SWZ((mw * 32 + mt * 16 + (lane & 15)) * 128 + abyte);
                LDSM_X4(aH[mt], sb + 81920 + o);
                LDSM_X4(aL[mt], sb + 90112 + o);
            }
            uint32_t ov = SWZ((ks * 16 + (lane & 15)) * 128 + nw * 32 + (lane >> 4) * 16);
            uint32_t t4[4], u4[4];
            LDSM_X4_T(t4, sb + 65536 + ov);
            LDSM_X4_T(u4, sb + 73728 + ov);
            uint32_t bh[2][2] = {{t4[0], t4[1]}, {t4[2], t4[3]}};
            uint32_t bl[2][2] = {{u4[0], u4[1]}, {u4[2], u4[3]}};
#pragma unroll
            for (int mt = 0; mt < 2; mt++)
#pragma unroll
                for (int nt = 0; nt < 2; nt++) {
                    MMA16816(accY[mt][nt], aH[mt], bh[nt]);
                    MMA16816(accY[mt][nt], aH[mt], bl[nt]);
                    MMA16816(accY[mt][nt], aL[mt], bh[nt]);
                }
        }
        __syncthreads();
    }

    int grp = lane >> 2;
#pragma unroll
    for (int mt = 0; mt < 2; mt++)
#pragma unroll
        for (int qh = 0; qh < 2; qh++) {
            float va = sAl[mt][qh], vs = sSl[mt][qh];
            va += __shfl_xor_sync(0xFFFFFFFFu, va, 1);
            va += __shfl_xor_sync(0xFFFFFFFFu, va, 2);
            vs += __shfl_xor_sync(0xFFFFFFFFu, vs, 1);
            vs += __shfl_xor_sync(0xFFFFFFFFu, vs, 2);
            if ((lane & 3) == 0) {
                int trow = mw * 32 + mt * 16 + grp + qh * 8;
                atomicAdd(&redA[trow], va);
                atomicAdd(&redS[trow], vs);
            }
        }
    __syncthreads();

    int qp = lane & 3;
#pragma unroll
    for (int mt = 0; mt < 2; mt++) {
        int r0 = mw * 32 + mt * 16 + grp;
        int r1 = r0 + 8;
        float sc0 = fmaxf(redA[r0], 1e-12f) / fmaxf(redS[r0], 1e-12f);
        float sc1 = fmaxf(redA[r1], 1e-12f) / fmaxf(redS[r1], 1e-12f);
#pragma unroll
        for (int nt = 0; nt < 2; nt++) {
            float* d = accY[mt][nt];
            int col = nw * 16 + nt * 8 + qp * 2;
            *(float2*)&y[(size_t)(t0 + r0) * 1024 + hb + col] =
                make_float2(d[0] * sc0, d[1] * sc0);
            *(float2*)&y[(size_t)(t0 + r1) * 1024 + hb + col] =
                make_float2(d[2] * sc1, d[3] * sc1);
        }
    }
}

// ---------------- 10. groupnorm + gate -> bf16 hi/lo ----------------
__global__ __launch_bounds__(256) void gnorm_k(const float* __restrict__ y,
                                               const float* __restrict__ g,
                                               const float* __restrict__ ln_g,
                                               const float* __restrict__ ln_b,
                                               __nv_bfloat16* __restrict__ ygHi,
                                               __nv_bfloat16* __restrict__ ygLo) {
    int gw = (blockIdx.x * 256 + threadIdx.x) >> 5;
    int lane = threadIdx.x & 31;
    int t = gw >> 4, h = gw & 15;
    size_t off = (size_t)t * 1024 + h * 64 + lane * 2;
    float2 vv = *(const float2*)(y + off);
    float s = vv.x + vv.y;
    float sq = vv.x * vv.x + vv.y * vv.y;
#pragma unroll
    for (int o = 16; o > 0; o >>= 1) {
        s  += __shfl_xor_sync(0xFFFFFFFFu, s, o);
        sq += __shfl_xor_sync(0xFFFFFFFFu, sq, o);
    }
    float mu = s * (1.f / 64.f);
    float var = sq * (1.f / 64.f) - mu * mu;
    float inv = rsqrtf(var + 6.4e-4f);
    int d = h * 64 + lane * 2;
    float2 gg = *(const float2*)(g + (size_t)t * 1024 + d);
    float ox = ((vv.x - mu) * inv * ln_g[d]     + ln_b[d])     * gg.x;
    float oy = ((vv.y - mu) * inv * ln_g[d + 1] + ln_b[d + 1]) * gg.y;
    __nv_bfloat162 hh, ll;
    split2(ox, oy, &hh, &ll);
    *(__nv_bfloat162*)(ygHi + off) = hh;
    *(__nv_bfloat162*)(ygLo + off) = ll;
}

// ---------------- launch ----------------
extern "C" void kernel_launch(void* const* d_in, const int* in_sizes, int n_in,
                              void* d_out, int out_size) {
    const float* x          = (const float*)d_in[0];
    const float* maa_x      = (const float*)d_in[1];
    const float* maa_w      = (const float*)d_in[2];
    const float* maa_k      = (const float*)d_in[3];
    const float* maa_v      = (const float*)d_in[4];
    const float* maa_r      = (const float*)d_in[5];
    const float* maa_g      = (const float*)d_in[6];
    const float* maa_w1     = (const float*)d_in[7];
    const float* maa_w2     = (const float*)d_in[8];
    const float* time_decay = (const float*)d_in[9];
    const float* decay_w1   = (const float*)d_in[10];
    const float* decay_w2   = (const float*)d_in[11];
    const float* log_tau    = (const float*)d_in[12];
    const float* Wr         = (const float*)d_in[13];
    const float* Wk         = (const float*)d_in[14];
    const float* Wv         = (const float*)d_in[15];
    const float* Wg         = (const float*)d_in[16];
    const float* Wo         = (const float*)d_in[17];
    const float* ln_g       = (const float*)d_in[18];
    const float* ln_b       = (const float*)d_in[19];

    float* S = nullptr;
    cudaGetSymbolAddress((void**)&S, g_scratch);
    float* dxb   = S + OFF_DX;
    float* zb    = S + OFF_Z;
    float* xwb   = S + OFF_XW;
    float* rkvg  = S + OFF_RKVG;
    float* wb    = S + OFF_W;
    float* csb   = S + OFF_CS;
    float* yb    = S + OFF_Y;
    float* xxxb  = S + OFF_XXX;
    float* wmidb = S + OFF_WMID;
    __nv_bfloat16* actHi = (__nv_bfloat16*)(S + OFF_ACTHI);
    __nv_bfloat16* actLo = (__nv_bfloat16*)(S + OFF_ACTLO);
    __nv_bfloat16* wtHi  = (__nv_bfloat16*)(S + OFF_WTHI);
    __nv_bfloat16* wtLo  = (__nv_bfloat16*)(S + OFF_WTLO);
    __nv_bfloat16* ygHi  = (__nv_bfloat16*)(S + OFF_YGHI);
    __nv_bfloat16* ygLo  = (__nv_bfloat16*)(S + OFF_YGLO);
    __nv_bfloat16* bfB   = (__nv_bfloat16*)(S + OFF_BF);

    int gemm_smem = 98304;
    cudaFuncSetAttribute(gemm_mma_k, cudaFuncAttributeMaxDynamicSharedMemorySize, gemm_smem);
    int attn_smem = 98304;
    cudaFuncSetAttribute(attn_mma_k, cudaFuncAttributeMaxDynamicSharedMemorySize, attn_smem);

    prep_k<<<(TD + 255) / 256, 256>>>(x, maa_x, dxb, zb);
    xxx_k<<<TTOK / 4, 160>>>(zb, maa_w1, xxxb);
    mix_k<<<TTOK / 4, 256>>>(x, dxb, xxxb, maa_w2,
                             maa_w, maa_k, maa_v, maa_r, maa_g, xwb, actHi, actLo);
    {
        dim3 grid(32, 32, 5);
        conv_wt_k<<<grid, 256>>>(Wr, Wk, Wv, Wg, Wo, wtHi, wtLo);
    }
    {
        dim3 grid(16, 16, 4);
        gemm_mma_k<<<grid, 256, gemm_smem>>>(actHi, actLo, wtHi, wtLo, rkvg, 3,
                                             bfB + (size_t)8 * TD, bfB + (size_t)9 * TD, 2);
    }
    decay1_k<<<TTOK / 8, 256>>>(xwb, decay_w1, wmidb);
    decay2_k<<<TTOK / 4, 256>>>(wmidb, decay_w2, time_decay, wb);
    cumsum_k<<<DDIM / 32, 1024>>>(wb, csb);
    premult_bf_k<<<(TD + 255) / 256, 256>>>(rkvg, rkvg + (size_t)TD, wb, csb, bfB);
    {
        dim3 grid(32, 16);
        attn_mma_k<<<grid, 256, attn_smem>>>(bfB, log_tau, yb);
    }
    gnorm_k<<<(TTOK * 16) / 8, 256>>>(yb, rkvg + (size_t)3 * TD, ln_g, ln_b, ygHi, ygLo);
    {
        dim3 grid(16, 16, 1);
        gemm_mma_k<<<grid, 256, gemm_smem>>>(ygHi, ygLo, wtHi + (size_t)4 * 1048576,
                                             wtLo + (size_t)4 * 1048576,
                                             (float*)d_out, -1, nullptr, nullptr, -1);
    }
}

// round 10
// speedup vs baseline: 1.3152x; 1.0435x over previous
#include <cuda_runtime.h>
#include <cuda_bf16.h>
#include <math.h>
#include <stdint.h>

#define TTOK 2048
#define DDIM 1024
#define TD (TTOK*DDIM)

// ---------------- scratch (static device memory; no allocations) ----------------
__device__ float g_scratch[68157440];

#define OFF_DX    ((size_t)0)
#define OFF_Z     ((size_t)TD)
#define OFF_XW    ((size_t)2*TD)
#define OFF_RKVG  ((size_t)7*TD)
#define OFF_W     ((size_t)11*TD)
#define OFF_CS    ((size_t)12*TD)
#define OFF_Y     ((size_t)17*TD)
#define OFF_XXX   ((size_t)19*TD)
#define OFF_WMID  (OFF_XXX + (size_t)TTOK*160)
#define OFF_ACTHI ((size_t)20*TD)
#define OFF_ACTLO ((size_t)22*TD)
#define OFF_WTHI  ((size_t)24*TD)
#define OFF_WTLO  (OFF_WTHI + (size_t)2621440)
#define OFF_YGHI  (OFF_WTLO + (size_t)2621440)
#define OFF_YGLO  (OFF_YGHI + (size_t)(TD/2))
#define OFF_BF    (OFF_YGLO + (size_t)(TD/2))

static __device__ __forceinline__ float clip60(float x) {
    return fminf(fmaxf(x, -60.f), 60.f);
}
static __device__ __forceinline__ uint32_t smem_u32(const void* p) {
    uint32_t a;
    asm("{ .reg .u64 t; cvta.to.shared.u64 t, %1; cvt.u32.u64 %0, t; }" : "=r"(a) : "l"(p));
    return a;
}

#define LDSM_X4(r, addr) \
    asm volatile("ldmatrix.sync.aligned.m8n8.x4.shared.b16 {%0,%1,%2,%3}, [%4];" \
                 : "=r"((r)[0]), "=r"((r)[1]), "=r"((r)[2]), "=r"((r)[3]) : "r"(addr))
#define LDSM_X4_T(r, addr) \
    asm volatile("ldmatrix.sync.aligned.m8n8.x4.trans.shared.b16 {%0,%1,%2,%3}, [%4];" \
                 : "=r"((r)[0]), "=r"((r)[1]), "=r"((r)[2]), "=r"((r)[3]) : "r"(addr))
#define MMA16816(d, a, b) \
    asm volatile("mma.sync.aligned.m16n8k16.row.col.f32.bf16.bf16.f32 " \
                 "{%0,%1,%2,%3}, {%4,%5,%6,%7}, {%8,%9}, {%0,%1,%2,%3};" \
                 : "+f"((d)[0]), "+f"((d)[1]), "+f"((d)[2]), "+f"((d)[3]) \
                 : "r"((a)[0]), "r"((a)[1]), "r"((a)[2]), "r"((a)[3]), \
                   "r"((b)[0]), "r"((b)[1]))
#define CPASYNC16(s, g) \
    asm volatile("cp.async.cg.shared.global [%0], [%1], 16;" :: "r"(s), "l"(g))
#define CPCOMMIT() asm volatile("cp.async.commit_group;" ::: "memory")
#define CPWAIT1()  asm volatile("cp.async.wait_group 1;" ::: "memory")
#define CPWAIT0()  asm volatile("cp.async.wait_group 0;" ::: "memory")
#define SWZ(o) ((o) ^ (((o) >> 3) & 0x70))

static __device__ __forceinline__ void split2(float a, float b,
                                              __nv_bfloat162* hi, __nv_bfloat162* lo) {
    __nv_bfloat162 h, l;
    h.x = __float2bfloat16(a);
    h.y = __float2bfloat16(b);
    l.x = __float2bfloat16(a - __bfloat162float(h.x));
    l.y = __float2bfloat16(b - __bfloat162float(h.y));
    *hi = h; *lo = l;
}
static __device__ __forceinline__ uint32_t packsplit(float a, float b, uint32_t* lo) {
    __nv_bfloat162 h, l;
    split2(a, b, &h, &l);
    *lo = *(uint32_t*)&l;
    return *(uint32_t*)&h;
}

// ---------------- 1. token shift + z ----------------
__global__ __launch_bounds__(256) void prep_k(const float* __restrict__ x,
                                              const float* __restrict__ maa_x,
                                              float* __restrict__ dx,
                                              float* __restrict__ z) {
    int idx = blockIdx.x * 256 + threadIdx.x;
    if (idx >= TD) return;
    int t = idx >> 10;
    int d = idx & 1023;
    float xv = x[idx];
    float prev = (t > 0) ? x[idx - 1024] : 0.f;
    float nxt  = (t < TTOK - 1) ? x[idx + 1024] : 0.f;
    float dxv = 0.5f * (prev + nxt) - xv;
    dx[idx] = dxv;
    z[idx]  = xv + dxv * maa_x[d];
}

// ---------------- 2. xxx = tanh(z @ maa_w1) ----------------
__global__ __launch_bounds__(160) void xxx_k(const float* __restrict__ z,
                                             const float* __restrict__ w1,
                                             float* __restrict__ xxx) {
    __shared__ float zs[4][1024];
    int t0 = blockIdx.x * 4;
    int tid = threadIdx.x;
    for (int i = tid; i < 4 * 1024; i += 160) {
        int r = i >> 10, c = i & 1023;
        zs[r][c] = z[(size_t)(t0 + r) * 1024 + c];
    }
    __syncthreads();
    float acc[4] = {0.f, 0.f, 0.f, 0.f};
    for (int d = 0; d < 1024; d++) {
        float w = w1[d * 160 + tid];
        acc[0] += zs[0][d] * w;
        acc[1] += zs[1][d] * w;
        acc[2] += zs[2][d] * w;
        acc[3] += zs[3][d] * w;
    }
#pragma unroll
    for (int r = 0; r < 4; r++)
        xxx[(size_t)(t0 + r) * 160 + tid] = tanhf(acc[r]);
}

// ---------------- 3. mixer ----------------
__global__ __launch_bounds__(256) void mix_k(const float* __restrict__ x,
                                             const float* __restrict__ dx,
                                             const float* __restrict__ xxx,
                                             const float* __restrict__ w2,
                                             const float* __restrict__ maa_w,
                                             const float* __restrict__ maa_k,
                                             const float* __restrict__ maa_v,
                                             const float* __restrict__ maa_r,
                                             const float* __restrict__ maa_g,
                                             float* __restrict__ xw,
                                             __nv_bfloat16* __restrict__ actHi,
                                             __nv_bfloat16* __restrict__ actLo) {
    __shared__ float xs[4][160];
    int t0 = blockIdx.x * 4;
    int tid = threadIdx.x;
    for (int i = tid; i < 640; i += 256) {
        int r = i / 160, c = i - r * 160;
        xs[r][c] = xxx[(size_t)(t0 + r) * 160 + c];
    }
    __syncthreads();
    int d = tid * 4;
    float4 xv[4], dxv[4];
#pragma unroll
    for (int r = 0; r < 4; r++) {
        xv[r]  = *(const float4*)(x  + (size_t)(t0 + r) * 1024 + d);
        dxv[r] = *(const float4*)(dx + (size_t)(t0 + r) * 1024 + d);
    }
#pragma unroll
    for (int f = 0; f < 5; f++) {
        float4 acc[4];
#pragma unroll
        for (int r = 0; r < 4; r++) acc[r] = make_float4(0.f, 0.f, 0.f, 0.f);
        for (int mi = 0; mi < 32; mi++) {
            float4 w = *(const float4*)(w2 + (size_t)(f * 32 + mi) * 1024 + d);
#pragma unroll
            for (int r = 0; r < 4; r++) {
                float s = xs[r][f * 32 + mi];
                acc[r].x += s * w.x; acc[r].y += s * w.y;
                acc[r].z += s * w.z; acc[r].w += s * w.w;
            }
        }
        const float* maa = (f == 0) ? maa_w : (f == 1) ? maa_k : (f == 2) ? maa_v
                         : (f == 3) ? maa_r : maa_g;
        float4 mv = *(const float4*)(maa + d);
        int slot = (f == 3) ? 0 : (f == 1) ? 1 : (f == 2) ? 2 : 3;
#pragma unroll
        for (int r = 0; r < 4; r++) {
            float4 o;
            o.x = xv[r].x + dxv[r].x * (mv.x + acc[r].x);
            o.y = xv[r].y + dxv[r].y * (mv.y + acc[r].y);
            o.z = xv[r].z + dxv[r].z * (mv.z + acc[r].z);
            o.w = xv[r].w + dxv[r].w * (mv.w + acc[r].w);
            if (f == 0) {
                *(float4*)(xw + (size_t)(t0 + r) * 1024 + d) = o;
            } else {
                size_t ofs = (size_t)slot * TD + (size_t)(t0 + r) * 1024 + d;
                __nv_bfloat162 h0, l0, h1, l1;
                split2(o.x, o.y, &h0, &l0);
                split2(o.z, o.w, &h1, &l1);
                *(__nv_bfloat162*)(actHi + ofs)     = h0;
                *(__nv_bfloat162*)(actHi + ofs + 2) = h1;
                *(__nv_bfloat162*)(actLo + ofs)     = l0;
                *(__nv_bfloat162*)(actLo + ofs + 2) = l1;
            }
        }
    }
}

// ---------------- weight transpose + split ----------------
__global__ __launch_bounds__(256) void conv_wt_k(const float* __restrict__ W0,
                                                 const float* __restrict__ W1,
                                                 const float* __restrict__ W2,
                                                 const float* __restrict__ W3,
                                                 const float* __restrict__ W4,
                                                 __nv_bfloat16* __restrict__ hi,
                                                 __nv_bfloat16* __restrict__ lo) {
    __shared__ float tile[32][33];
    int z = blockIdx.z;
    const float* W = (z == 0) ? W0 : (z == 1) ? W1 : (z == 2) ? W2 : (z == 3) ? W3 : W4;
    int k0 = blockIdx.x * 32, n0 = blockIdx.y * 32;
    int tx = threadIdx.x & 31, ty = threadIdx.x >> 5;
#pragma unroll
    for (int i = 0; i < 32; i += 8)
        tile[ty + i][tx] = W[(size_t)(k0 + ty + i) * 1024 + n0 + tx];
    __syncthreads();
    size_t base = (size_t)z * 1048576;
#pragma unroll
    for (int i = 0; i < 32; i += 8) {
        float v = tile[tx][ty + i];
        size_t o = base + (size_t)(n0 + ty + i) * 1024 + k0 + tx;
        __nv_bfloat16 h = __float2bfloat16(v);
        hi[o] = h;
        lo[o] = __float2bfloat16(v - __bfloat162float(h));
    }
}

// ---------------- mma.sync split-bf16 GEMM: 128x64 CTA tile, occ 2 ----------------
__global__ __launch_bounds__(256, 2)
void gemm_mma_k(const __nv_bfloat16* __restrict__ aHi,
                const __nv_bfloat16* __restrict__ aLo,
                const __nv_bfloat16* __restrict__ bHi,
                const __nv_bfloat16* __restrict__ bLo,
                float* __restrict__ C, int siluZ,
                __nv_bfloat16* __restrict__ vHi,
                __nv_bfloat16* __restrict__ vLo, int vz) {
    extern __shared__ unsigned char smraw[];
    const int tid = threadIdx.x;
    const int z = blockIdx.z;
    const int bm = blockIdx.y * 128;
    const int bn = blockIdx.x * 64;
    const __nv_bfloat16* srcA[2] = { aHi + (size_t)z * TD, aLo + (size_t)z * TD };
    const __nv_bfloat16* srcB[2] = { bHi + (size_t)z * 1048576, bLo + (size_t)z * 1048576 };
    float* Cz = C + (size_t)z * TD;

    const uint32_t sbase = smem_u32(smraw);
    const int w = tid >> 5, lane = tid & 31;
    const int mw = w >> 1, nw = w & 1;

    float acc[2][4][4];
#pragma unroll
    for (int mt = 0; mt < 2; mt++)
#pragma unroll
        for (int nt = 0; nt < 4; nt++)
#pragma unroll
            for (int q = 0; q < 4; q++) acc[mt][nt][q] = 0.f;

    auto issue = [&](int c) {
        uint32_t stg = sbase + (c & 1) * 49152;
        int k0 = c * 64;
#pragma unroll 4
        for (int i = tid; i < 3072; i += 256) {
            const char* g;
            uint32_t dst;
            if (i < 2048) {
                int tile = i >> 10, idx = i & 1023;
                int row = idx >> 3, ch = idx & 7;
                g = (const char*)srcA[tile] + ((size_t)(bm + row) * 1024 + k0) * 2 + ch * 16;
                dst = stg + tile * 16384 + SWZ(row * 128 + ch * 16);
            } else {
                int j = i - 2048;
                int tile = j >> 9, idx = j & 511;
                int row = idx >> 3, ch = idx & 7;
                g = (const char*)srcB[tile] + ((size_t)(bn + row) * 1024 + k0) * 2 + ch * 16;
                dst = stg + 32768 + tile * 8192 + SWZ(row * 128 + ch * 16);
            }
            CPASYNC16(dst, g);
        }
        CPCOMMIT();
    };

    issue(0);
    issue(1);

    for (int c = 0; c < 16; c++) {
        if (c < 15) CPWAIT1(); else CPWAIT0();
        __syncthreads();
        uint32_t st = sbase + (c & 1) * 49152;
#pragma unroll
        for (int kk = 0; kk < 4; kk++) {
            int cb = kk * 2 + (lane >> 4);
            uint32_t ah[2][4], al[2][4];
#pragma unroll
            for (int mt = 0; mt < 2; mt++) {
                int r = mw * 32 + mt * 16 + (lane & 15);
                uint32_t o = SWZ(r * 128 + cb * 16);
                LDSM_X4(ah[mt], st + o);
                LDSM_X4(al[mt], st + 16384 + o);
            }
            uint32_t bh[4][2], bl[4][2];
#pragma unroll
            for (int p = 0; p < 2; p++) {
                int r = nw * 32 + p * 16 + (lane & 15);
                uint32_t o = SWZ(r * 128 + cb * 16);
                uint32_t t4[4];
                LDSM_X4(t4, st + 32768 + o);
                bh[2 * p][0] = t4[0]; bh[2 * p][1] = t4[2];
                bh[2 * p + 1][0] = t4[1]; bh[2 * p + 1][1] = t4[3];
                LDSM_X4(t4, st + 40960 + o);
                bl[2 * p][0] = t4[0]; bl[2 * p][1] = t4[2];
                bl[2 * p + 1][0] = t4[1]; bl[2 * p + 1][1] = t4[3];
            }
#pragma unroll
            for (int mt = 0; mt < 2; mt++)
#pragma unroll
                for (int nt = 0; nt < 4; nt++) {
                    MMA16816(acc[mt][nt], ah[mt], bh[nt]);
                    MMA16816(acc[mt][nt], ah[mt], bl[nt]);
                    MMA16816(acc[mt][nt], al[mt], bh[nt]);
                }
        }
        __syncthreads();
        if (c + 2 < 16) issue(c + 2);
    }

    bool silu = (z == siluZ);
    bool isv = (z == vz);
    int r0 = bm + mw * 32, c0 = bn + nw * 32;
#pragma unroll
    for (int mt = 0; mt < 2; mt++)
#pragma unroll
        for (int nt = 0; nt < 4; nt++) {
            float* d = acc[mt][nt];
            int row = r0 + mt * 16 + (lane >> 2);
            int col = c0 + nt * 8 + (lane & 3) * 2;
            if (isv) {
                __nv_bfloat162 h, l;
                split2(d[0], d[1], &h, &l);
                *(__nv_bfloat162*)(vHi + (size_t)row * 1024 + col) = h;
                *(__nv_bfloat162*)(vLo + (size_t)row * 1024 + col) = l;
                split2(d[2], d[3], &h, &l);
                *(__nv_bfloat162*)(vHi + (size_t)(row + 8) * 1024 + col) = h;
                *(__nv_bfloat162*)(vLo + (size_t)(row + 8) * 1024 + col) = l;
            } else {
                if (silu) {
#pragma unroll
                    for (int q = 0; q < 4; q++) d[q] = d[q] / (1.f + expf(-d[q]));
                }
                *(float2*)&Cz[(size_t)row * 1024 + col]       = make_float2(d[0], d[1]);
                *(float2*)&Cz[(size_t)(row + 8) * 1024 + col] = make_float2(d[2], d[3]);
            }
        }
}

// ---------------- 5. decay MLP stage 1 ----------------
__global__ __launch_bounds__(256) void decay1_k(const float* __restrict__ xw,
                                                const float* __restrict__ dw1,
                                                float* __restrict__ wmid) {
    __shared__ float xs[8][1024];
    __shared__ float part[4][64][8];
    int t0 = blockIdx.x * 8;
    int tid = threadIdx.x;
    for (int i = tid; i < 8 * 256; i += 256) {
        int r = i >> 8;
        int c4 = (i & 255) * 4;
        *(float4*)(&xs[r][c4]) = *(const float4*)(xw + (size_t)(t0 + r) * 1024 + c4);
    }
    __syncthreads();
    int n = tid & 63;
    int kq = tid >> 6;
    int kbase = kq * 256;
    float acc[8] = {0.f, 0.f, 0.f, 0.f, 0.f, 0.f, 0.f, 0.f};
    for (int dd = 0; dd < 256; dd++) {
        int d = kbase + dd;
        float w = dw1[d * 64 + n];
#pragma unroll
        for (int r = 0; r < 8; r++) acc[r] += xs[r][d] * w;
    }
#pragma unroll
    for (int r = 0; r < 8; r++) part[kq][n][r] = acc[r];
    __syncthreads();
    for (int i = tid; i < 512; i += 256) {
        int nn = i & 63, r = i >> 6;
        float s = part[0][nn][r] + part[1][nn][r] + part[2][nn][r] + part[3][nn][r];
        wmid[(size_t)(t0 + r) * 64 + nn] = tanhf(s);
    }
}

// ---------------- 6. decay MLP stage 2 ----------------
__global__ __launch_bounds__(256) void decay2_k(const float* __restrict__ wmid,
                                                const float* __restrict__ dw2,
                                                const float* __restrict__ td,
                                                float* __restrict__ w) {
    __shared__ float ws[4][64];
    int t0 = blockIdx.x * 4;
    int tid = threadIdx.x;
    {
        int r = tid >> 6, c = tid & 63;
        ws[r][c] = wmid[(size_t)(t0 + r) * 64 + c];
    }
    __syncthreads();
    int d = tid * 4;
    float4 tdv = *(const float4*)(td + d);
    float4 acc[4];
#pragma unroll
    for (int r = 0; r < 4; r++) acc[r] = tdv;
    for (int j = 0; j < 64; j++) {
        float4 wv = *(const float4*)(dw2 + (size_t)j * 1024 + d);
#pragma unroll
        for (int r = 0; r < 4; r++) {
            float s = ws[r][j];
            acc[r].x += s * wv.x; acc[r].y += s * wv.y;
            acc[r].z += s * wv.z; acc[r].w += s * wv.w;
        }
    }
#pragma unroll
    for (int r = 0; r < 4; r++)
        *(float4*)(w + (size_t)(t0 + r) * 1024 + d) = acc[r];
}

// ---------------- 7. per-channel cumsum ----------------
__global__ __launch_bounds__(1024) void cumsum_k(const float* __restrict__ w,
                                                 float* __restrict__ cs) {
    __shared__ float seg[32][33];
    int c = threadIdx.x & 31;
    int j = threadIdx.x >> 5;
    int d = blockIdx.x * 32 + c;
    int tb = j * 64;
    float s = 0.f;
    for (int t = 0; t < 64; t++)
        s -= expf(w[(size_t)(tb + t) * 1024 + d]);
    seg[j][c] = s;
    __syncthreads();
    if (j == 0) {
        float run = 0.f;
        for (int jj = 0; jj < 32; jj++) {
            float tmp = seg[jj][c];
            seg[jj][c] = run;
            run += tmp;
        }
    }
    __syncthreads();
    float run = seg[j][c];
    for (int t = 0; t < 64; t++) {
        run -= expf(w[(size_t)(tb + t) * 1024 + d]);
        cs[(size_t)(tb + t) * 1024 + d] = run;
    }
}

// ---------------- 8. premult -> bf16 hi/lo operands ----------------
__global__ __launch_bounds__(256) void premult_bf_k(const float* __restrict__ r,
                                                    const float* __restrict__ k,
                                                    const float* __restrict__ w,
                                                    const float* __restrict__ cs,
                                                    __nv_bfloat16* __restrict__ bfB) {
    int idx = blockIdx.x * 256 + threadIdx.x;
    if (idx >= TD) return;
    int d = idx & 1023;
    size_t midoff = (size_t)(TTOK / 2) * 1024 + d;
    float csv = cs[idx];
    float csm = cs[midoff];
    float wh   = -expf(w[idx]);
    float whm  = -expf(w[midoff]);
    float csf = clip60(csv - csm);
    float csb = clip60((csv - wh) - (csm - whm));
    float rv = r[idx], kv = k[idx];
    float vals[4];
    vals[0] = rv * expf(csf);
    vals[1] = kv * expf(-csf);
    vals[2] = rv * expf(-csb);
    vals[3] = kv * expf(csb);
#pragma unroll
    for (int j = 0; j < 4; j++) {
        __nv_bfloat16 h = __float2bfloat16(vals[j]);
        bfB[(size_t)(2 * j) * TD + idx] = h;
        bfB[(size_t)(2 * j + 1) * TD + idx] = __float2bfloat16(vals[j] - __bfloat162float(h));
    }
}

// ---------------- 9. attention: FA2-style P-register reuse, warp grid 4(t) x 2(s) ----------------
// smem (bytes): R1H 0, R1L 8K, R2H 16K, R2L 24K,
//               K1H 32K, K1L 40K, K2H 48K, K2L 56K, VH 64K, VL 72K.  80K dynamic.
__global__ __launch_bounds__(256, 2) void attn_mma_k(const __nv_bfloat16* __restrict__ bfB,
                                                     const float* __restrict__ log_tau,
                                                     float* __restrict__ y) {
    extern __shared__ unsigned char sm8[];
    __shared__ float redA[64], redS[64];
    const uint32_t sb = smem_u32(sm8);
    int h = blockIdx.y, it = blockIdx.x;
    int t0 = it * 64;
    int tid = threadIdx.x, w = tid >> 5, lane = tid & 31;
    int mw = w >> 1, sw = w & 1;    // 4 t-warps x 2 s-warps
    size_t hb = (size_t)h * 64;
    float tau = expf(log_tau[h]);
    int grp = lane >> 2, qp = lane & 3;

    if (tid < 64) { redA[tid] = 0.f; redS[tid] = 0.f; }

    // r tiles: arrays {0,1,4,5} -> 0..32K
    for (int i = tid; i < 2048; i += 256) {
        int tile = i >> 9, idx = i & 511;
        int row = idx >> 3, ch = idx & 7;
        int arr = (tile & 1) + (tile >> 1) * 4;
        const char* g = (const char*)(bfB + (size_t)arr * TD
                        + (size_t)(t0 + row) * 1024 + hb) + ch * 16;
        CPASYNC16(sb + tile * 8192 + SWZ(row * 128 + ch * 16), g);
    }
    CPCOMMIT();
    CPWAIT0();
    __syncthreads();

    float accY[8][4];
#pragma unroll
    for (int nt = 0; nt < 8; nt++)
#pragma unroll
        for (int q = 0; q < 4; q++) accY[nt][q] = 0.f;
    float sA[2] = {0.f, 0.f};
    float sS[2] = {0.f, 0.f};

    for (int jt = 0; jt < 32; jt++) {
        int s0 = jt * 64;
        bool needF = (jt <= it);
        bool needB = (jt >= it);
        for (int i = tid; i < 3072; i += 256) {
            int tile = i >> 9;
            if (tile < 2 && !needF) continue;
            if (tile >= 2 && tile < 4 && !needB) continue;
            int idx = i & 511, row = idx >> 3, ch = idx & 7;
            int arr = (tile < 4) ? (2 + (tile & 1) + (tile >> 1) * 4) : (tile + 4);
            const char* g = (const char*)(bfB + (size_t)arr * TD
                            + (size_t)(s0 + row) * 1024 + hb) + ch * 16;
            CPASYNC16(sb + 32768 + tile * 8192 + SWZ(row * 128 + ch * 16), g);
        }
        CPCOMMIT();
        CPWAIT0();
        __syncthreads();

        float accF[4][4], accB[4][4];
#pragma unroll
        for (int nt = 0; nt < 4; nt++)
#pragma unroll
            for (int q = 0; q < 4; q++) { accF[nt][q] = 0.f; accB[nt][q] = 0.f; }

        // ---- scores: warp tile [16t x 32s] per direction ----
#pragma unroll
        for (int ks = 0; ks < 4; ks++) {
            uint32_t abyte = ks * 32 + (lane >> 4) * 16;
            uint32_t oA = SWZ((mw * 16 + (lane & 15)) * 128 + abyte);
            if (needF) {
                uint32_t aH[4], aL[4];
                LDSM_X4(aH, sb + oA);
                LDSM_X4(aL, sb + 8192 + oA);
                uint32_t bh[4][2], bl[4][2];
#pragma unroll
                for (int p = 0; p < 2; p++) {
                    uint32_t o = SWZ((sw * 32 + p * 16 + (lane & 15)) * 128 + abyte);
                    uint32_t t4[4], u4[4];
                    LDSM_X4(t4, sb + 32768 + o);
                    LDSM_X4(u4, sb + 40960 + o);
                    bh[2 * p][0] = t4[0]; bh[2 * p][1] = t4[2];
                    bh[2 * p + 1][0] = t4[1]; bh[2 * p + 1][1] = t4[3];
                    bl[2 * p][0] = u4[0]; bl[2 * p][1] = u4[2];
                    bl[2 * p + 1][0] = u4[1]; bl[2 * p + 1][1] = u4[3];
                }
#pragma unroll
                for (int nt = 0; nt < 4; nt++) {
                    MMA16816(accF[nt], aH, bh[nt]);
                    MMA16816(accF[nt], aH, bl[nt]);
                    MMA16816(accF[nt], aL, bh[nt]);
                }
            }
            if (needB) {
                uint32_t aH[4], aL[4];
                LDSM_X4(aH, sb + 16384 + oA);
                LDSM_X4(aL, sb + 24576 + oA);
                uint32_t bh[4][2], bl[4][2];
#pragma unroll
                for (int p = 0; p < 2; p++) {
                    uint32_t o = SWZ((sw * 32 + p * 16 + (lane & 15)) * 128 + abyte);
                    uint32_t t4[4], u4[4];
                    LDSM_X4(t4, sb + 49152 + o);
                    LDSM_X4(u4, sb + 57344 + o);
                    bh[2 * p][0] = t4[0]; bh[2 * p][1] = t4[2];
                    bh[2 * p + 1][0] = t4[1]; bh[2 * p + 1][1] = t4[3];
                    bl[2 * p][0] = u4[0]; bl[2 * p][1] = u4[2];
                    bl[2 * p + 1][0] = u4[1]; bl[2 * p + 1][1] = u4[3];
                }
#pragma unroll
                for (int nt = 0; nt < 4; nt++) {
                    MMA16816(accB[nt], aH, bh[nt]);
                    MMA16816(accB[nt], aH, bl[nt]);
                    MMA16816(accB[nt], aL, bh[nt]);
                }
            }
        }

        // ---- elementwise + build P fragments in registers ----
        uint32_t pH[2][4], pL[2][4];
#pragma unroll
        for (int nt = 0; nt < 4; nt++) {
            float ash[4];
#pragma unroll
            for (int q = 0; q < 4; q++) {
                int trow = t0 + mw * 16 + grp + (q >> 1) * 8;
                int scol = s0 + sw * 32 + nt * 8 + qp * 2 + (q & 1);
                float val;
                if (jt < it) val = accF[nt][q];
                else if (jt > it) val = accB[nt][q];
                else val = (scol > trow) ? accB[nt][q] : accF[nt][q];
                float a = fmaxf(val, 0.f);
                sA[q >> 1] += a;
                float as = (a > 0.f) ? __powf(a + 1e-12f, tau) : 0.f;
                sS[q >> 1] += as;
                ash[q] = as;
            }
            int kc = nt >> 1, half = nt & 1;
            pH[kc][half * 2]     = packsplit(ash[0], ash[1], &pL[kc][half * 2]);
            pH[kc][half * 2 + 1] = packsplit(ash[2], ash[3], &pL[kc][half * 2 + 1]);
        }

        // ---- AV: accY[16t x 64d partial over this warp's 32 s] ----
#pragma unroll
        for (int kc = 0; kc < 2; kc++) {
#pragma unroll
            for (int dblk = 0; dblk < 4; dblk++) {
                uint32_t ov = SWZ((sw * 32 + kc * 16 + (lane & 15)) * 128
                                  + dblk * 32 + (lane >> 4) * 16);
                uint32_t t4[4], u4[4];
                LDSM_X4_T(t4, sb + 65536 + ov);
                LDSM_X4_T(u4, sb + 73728 + ov);
                uint32_t bvh[2][2] = {{t4[0], t4[1]}, {t4[2], t4[3]}};
                uint32_t bvl[2][2] = {{u4[0], u4[1]}, {u4[2], u4[3]}};
#pragma unroll
                for (int x = 0; x < 2; x++) {
                    int nt = dblk * 2 + x;
                    MMA16816(accY[nt], pH[kc], bvh[x]);
                    MMA16816(accY[nt], pH[kc], bvl[x]);
                    MMA16816(accY[nt], pL[kc], bvh[x]);
                }
            }
        }
        __syncthreads();
    }

    // ---- reduce row sums (quad shfl + atomics over sw) ----
#pragma unroll
    for (int qh = 0; qh < 2; qh++) {
        float va = sA[qh], vs = sS[qh];
        va += __shfl_xor_sync(0xFFFFFFFFu, va, 1);
        va += __shfl_xor_sync(0xFFFFFFFFu, va, 2);
        vs += __shfl_xor_sync(0xFFFFFFFFu, vs, 1);
        vs += __shfl_xor_sync(0xFFFFFFFFu, vs, 2);
        if ((lane & 3) == 0) {
            int trow = mw * 16 + grp + qh * 8;
            atomicAdd(&redA[trow], va);
            atomicAdd(&redS[trow], vs);
        }
    }

    // ---- cross-sw reduction of accY via smem (reuse tile area) ----
    float* red = (float*)sm8;   // [64][64]
    __syncthreads();
    if (sw == 1) {
#pragma unroll
        for (int nt = 0; nt < 8; nt++) {
            int r0 = mw * 16 + grp;
            int col = nt * 8 + qp * 2;
            *(float2*)&red[(r0)     * 64 + col] = make_float2(accY[nt][0], accY[nt][1]);
            *(float2*)&red[(r0 + 8) * 64 + col] = make_float2(accY[nt][2], accY[nt][3]);
        }
    }
    __syncthreads();
    if (sw == 0) {
        int r0 = mw * 16 + grp;
        int r1 = r0 + 8;
        float sc0 = fmaxf(redA[r0], 1e-12f) / fmaxf(redS[r0], 1e-12f);
        float sc1 = fmaxf(redA[r1], 1e-12f) / fmaxf(redS[r1], 1e-12f);
#pragma unroll
        for (int nt = 0; nt < 8; nt++) {
            int col = nt * 8 + qp * 2;
            float2 o0 = *(float2*)&red[r0 * 64 + col];
            float2 o1 = *(float2*)&red[r1 * 64 + col];
            o0.x = (accY[nt][0] + o0.x) * sc0;
            o0.y = (accY[nt][1] + o0.y) * sc0;
            o1.x = (accY[nt][2] + o1.x) * sc1;
            o1.y = (accY[nt][3] + o1.y) * sc1;
            *(float2*)&y[(size_t)(t0 + r0) * 1024 + hb + col] = o0;
            *(float2*)&y[(size_t)(t0 + r1) * 1024 + hb + col] = o1;
        }
    }
}

// ---------------- 10. groupnorm + gate -> bf16 hi/lo ----------------
__global__ __launch_bounds__(256) void gnorm_k(const float* __restrict__ y,
                                               const float* __restrict__ g,
                                               const float* __restrict__ ln_g,
                                               const float* __restrict__ ln_b,
                                               __nv_bfloat16* __restrict__ ygHi,
                                               __nv_bfloat16* __restrict__ ygLo) {
    int gw = (blockIdx.x * 256 + threadIdx.x) >> 5;
    int lane = threadIdx.x & 31;
    int t = gw >> 4, h = gw & 15;
    size_t off = (size_t)t * 1024 + h * 64 + lane * 2;
    float2 vv = *(const float2*)(y + off);
    float s = vv.x + vv.y;
    float sq = vv.x * vv.x + vv.y * vv.y;
#pragma unroll
    for (int o = 16; o > 0; o >>= 1) {
        s  += __shfl_xor_sync(0xFFFFFFFFu, s, o);
        sq += __shfl_xor_sync(0xFFFFFFFFu, sq, o);
    }
    float mu = s * (1.f / 64.f);
    float var = sq * (1.f / 64.f) - mu * mu;
    float inv = rsqrtf(var + 6.4e-4f);
    int d = h * 64 + lane * 2;
    float2 gg = *(const float2*)(g + (size_t)t * 1024 + d);
    float ox = ((vv.x - mu) * inv * ln_g[d]     + ln_b[d])     * gg.x;
    float oy = ((vv.y - mu) * inv * ln_g[d + 1] + ln_b[d + 1]) * gg.y;
    __nv_bfloat162 hh, ll;
    split2(ox, oy, &hh, &ll);
    *(__nv_bfloat162*)(ygHi + off) = hh;
    *(__nv_bfloat162*)(ygLo + off) = ll;
}

// ---------------- launch ----------------
extern "C" void kernel_launch(void* const* d_in, const int* in_sizes, int n_in,
                              void* d_out, int out_size) {
    const float* x          = (const float*)d_in[0];
    const float* maa_x      = (const float*)d_in[1];
    const float* maa_w      = (const float*)d_in[2];
    const float* maa_k      = (const float*)d_in[3];
    const float* maa_v      = (const float*)d_in[4];
    const float* maa_r      = (const float*)d_in[5];
    const float* maa_g      = (const float*)d_in[6];
    const float* maa_w1     = (const float*)d_in[7];
    const float* maa_w2     = (const float*)d_in[8];
    const float* time_decay = (const float*)d_in[9];
    const float* decay_w1   = (const float*)d_in[10];
    const float* decay_w2   = (const float*)d_in[11];
    const float* log_tau    = (const float*)d_in[12];
    const float* Wr         = (const float*)d_in[13];
    const float* Wk         = (const float*)d_in[14];
    const float* Wv         = (const float*)d_in[15];
    const float* Wg         = (const float*)d_in[16];
    const float* Wo         = (const float*)d_in[17];
    const float* ln_g       = (const float*)d_in[18];
    const float* ln_b       = (const float*)d_in[19];

    float* S = nullptr;
    cudaGetSymbolAddress((void**)&S, g_scratch);
    float* dxb   = S + OFF_DX;
    float* zb    = S + OFF_Z;
    float* xwb   = S + OFF_XW;
    float* rkvg  = S + OFF_RKVG;
    float* wb    = S + OFF_W;
    float* csb   = S + OFF_CS;
    float* yb    = S + OFF_Y;
    float* xxxb  = S + OFF_XXX;
    float* wmidb = S + OFF_WMID;
    __nv_bfloat16* actHi = (__nv_bfloat16*)(S + OFF_ACTHI);
    __nv_bfloat16* actLo = (__nv_bfloat16*)(S + OFF_ACTLO);
    __nv_bfloat16* wtHi  = (__nv_bfloat16*)(S + OFF_WTHI);
    __nv_bfloat16* wtLo  = (__nv_bfloat16*)(S + OFF_WTLO);
    __nv_bfloat16* ygHi  = (__nv_bfloat16*)(S + OFF_YGHI);
    __nv_bfloat16* ygLo  = (__nv_bfloat16*)(S + OFF_YGLO);
    __nv_bfloat16* bfB   = (__nv_bfloat16*)(S + OFF_BF);

    int gemm_smem = 98304;
    cudaFuncSetAttribute(gemm_mma_k, cudaFuncAttributeMaxDynamicSharedMemorySize, gemm_smem);
    int attn_smem = 81920;
    cudaFuncSetAttribute(attn_mma_k, cudaFuncAttributeMaxDynamicSharedMemorySize, attn_smem);

    prep_k<<<(TD + 255) / 256, 256>>>(x, maa_x, dxb, zb);
    xxx_k<<<TTOK / 4, 160>>>(zb, maa_w1, xxxb);
    mix_k<<<TTOK / 4, 256>>>(x, dxb, xxxb, maa_w2,
                             maa_w, maa_k, maa_v, maa_r, maa_g, xwb, actHi, actLo);
    {
        dim3 grid(32, 32, 5);
        conv_wt_k<<<grid, 256>>>(Wr, Wk, Wv, Wg, Wo, wtHi, wtLo);
    }
    {
        dim3 grid(16, 16, 4);
        gemm_mma_k<<<grid, 256, gemm_smem>>>(actHi, actLo, wtHi, wtLo, rkvg, 3,
                                             bfB + (size_t)8 * TD, bfB + (size_t)9 * TD, 2);
    }
    decay1_k<<<TTOK / 8, 256>>>(xwb, decay_w1, wmidb);
    decay2_k<<<TTOK / 4, 256>>>(wmidb, decay_w2, time_decay, wb);
    cumsum_k<<<DDIM / 32, 1024>>>(wb, csb);
    premult_bf_k<<<(TD + 255) / 256, 256>>>(rkvg, rkvg + (size_t)TD, wb, csb, bfB);
    {
        dim3 grid(32, 16);
        attn_mma_k<<<grid, 256, attn_smem>>>(bfB, log_tau, yb);
    }
    gnorm_k<<<(TTOK * 16) / 8, 256>>>(yb, rkvg + (size_t)3 * TD, ln_g, ln_b, ygHi, ygLo);
    {
        dim3 grid(16, 16, 1);
        gemm_mma_k<<<grid, 256, gemm_smem>>>(ygHi, ygLo, wtHi + (size_t)4 * 1048576,
                                             wtLo + (size_t)4 * 1048576,
                                             (float*)d_out, -1, nullptr, nullptr, -1);
    }
}